// round 1
// baseline (speedup 1.0000x reference)
#include <cuda_runtime.h>

#define BB 4
#define CC 256
#define CI 128
#define TT 8192
#define NN 4096
#define BNT (BB*TT)

// Scratch (device globals; no allocation allowed)
__device__ float d_theta[BB*CI*TT];   // 16 MB
__device__ float d_phi[BB*CI*NN];     // 8 MB
__device__ float d_g[BB*CI*NN];       // 8 MB
__device__ float d_S[BB*CI*CI];       // 256 KB
__device__ float d_M[BB*CC*CI];       // 512 KB
__device__ float d_wy[BB*CC*TT];      // 32 MB
__device__ float d_sum[CC];
__device__ float d_sumsq[CC];
__device__ float d_scale[CC];
__device__ float d_shift[CC];

// ---------------------------------------------------------------------------
// K0: zero accumulators (S, sum, sumsq). Re-run each launch for determinism.
// ---------------------------------------------------------------------------
__global__ void k_init() {
    int i = blockIdx.x * blockDim.x + threadIdx.x;
    if (i < BB*CI*CI) d_S[i] = 0.0f;
    if (i < CC) { d_sum[i] = 0.0f; d_sumsq[i] = 0.0f; }
}

// ---------------------------------------------------------------------------
// K1: fused 1x1 convs. out(128 x Ttile) = W(128x256) @ x[b](256 x Ttile).
// blockIdx.y selects theta/phi/g. phi/g are maxpooled (stride-2) in registers.
// Tile: 128(o) x 128(t), K=256, BK=32, 256 threads, 8x8 microtile.
// ---------------------------------------------------------------------------
__global__ __launch_bounds__(256) void k_conv(
    const float* __restrict__ x,
    const float* __restrict__ Wt, const float* __restrict__ bt,
    const float* __restrict__ Wp, const float* __restrict__ bp,
    const float* __restrict__ Wg, const float* __restrict__ bg)
{
    __shared__ float As[32][132];  // As[k][o] = W[o][k0+k]
    __shared__ float Bs[32][128];  // Bs[k][t]

    const int tid = threadIdx.x;
    const int b   = blockIdx.z;
    const int w   = blockIdx.y;
    const int t0  = blockIdx.x * 128;

    const float* W    = (w == 0) ? Wt : ((w == 1) ? Wp : Wg);
    const float* bias = (w == 0) ? bt : ((w == 1) ? bp : bg);
    const float* xb   = x + (size_t)b * CC * TT;

    const int tx = tid & 15;
    const int ty = tid >> 4;

    float acc[8][8];
#pragma unroll
    for (int i = 0; i < 8; i++)
#pragma unroll
        for (int j = 0; j < 8; j++) acc[i][j] = 0.0f;

    for (int k0 = 0; k0 < CC; k0 += 32) {
        // Load W tile (128 o x 32 k), store transposed
#pragma unroll
        for (int i = 0; i < 4; i++) {
            int id = tid + i * 256;
            int o = id >> 3, q = id & 7;
            float4 v = *(const float4*)(W + (size_t)o * CC + k0 + q * 4);
            As[q*4+0][o] = v.x; As[q*4+1][o] = v.y;
            As[q*4+2][o] = v.z; As[q*4+3][o] = v.w;
        }
        // Load x tile (32 c x 128 t)
#pragma unroll
        for (int i = 0; i < 4; i++) {
            int id = tid + i * 256;
            int c = id >> 5, qt = id & 31;
            float4 v = *(const float4*)(xb + (size_t)(k0 + c) * TT + t0 + qt * 4);
            *(float4*)(&Bs[c][qt * 4]) = v;
        }
        __syncthreads();
#pragma unroll
        for (int kk = 0; kk < 32; kk++) {
            float a[8], bb[8];
#pragma unroll
            for (int i = 0; i < 8; i++) a[i] = As[kk][ty * 8 + i];
#pragma unroll
            for (int j = 0; j < 8; j++) bb[j] = Bs[kk][tx * 8 + j];
#pragma unroll
            for (int i = 0; i < 8; i++)
#pragma unroll
                for (int j = 0; j < 8; j++) acc[i][j] = fmaf(a[i], bb[j], acc[i][j]);
        }
        __syncthreads();
    }

    if (w == 0) {
        float* dst = d_theta + (size_t)b * CI * TT;
#pragma unroll
        for (int i = 0; i < 8; i++) {
            int o = ty * 8 + i;
            float bz = bias[o];
            float4 v0 = make_float4(acc[i][0]+bz, acc[i][1]+bz, acc[i][2]+bz, acc[i][3]+bz);
            float4 v1 = make_float4(acc[i][4]+bz, acc[i][5]+bz, acc[i][6]+bz, acc[i][7]+bz);
            *(float4*)(dst + (size_t)o * TT + t0 + tx * 8)     = v0;
            *(float4*)(dst + (size_t)o * TT + t0 + tx * 8 + 4) = v1;
        }
    } else {
        float* dst = ((w == 1) ? d_phi : d_g) + (size_t)b * CI * NN;
        int n0 = (t0 + tx * 8) >> 1;
#pragma unroll
        for (int i = 0; i < 8; i++) {
            int o = ty * 8 + i;
            float bz = bias[o];
            float4 v;
            v.x = fmaxf(acc[i][0], acc[i][1]) + bz;
            v.y = fmaxf(acc[i][2], acc[i][3]) + bz;
            v.z = fmaxf(acc[i][4], acc[i][5]) + bz;
            v.w = fmaxf(acc[i][6], acc[i][7]) + bz;
            *(float4*)(dst + (size_t)o * NN + n0) = v;
        }
    }
}

// ---------------------------------------------------------------------------
// K2: S[b,a,ci] = sum_n phi[b,a,n] * g[b,ci,n].  Split-K over n (32 slabs of
// 128), 128x128 output per block, atomicAdd into d_S.
// ---------------------------------------------------------------------------
__global__ __launch_bounds__(256) void k_S()
{
    __shared__ float As[16][132]; // As[kn][a]
    __shared__ float Bs[16][132]; // Bs[kn][ci]

    const int tid = threadIdx.x;
    const int b   = blockIdx.y;
    const int n0  = blockIdx.x * 128;
    const float* P = d_phi + (size_t)b * CI * NN;
    const float* G = d_g   + (size_t)b * CI * NN;
    const int tx = tid & 15, ty = tid >> 4;

    float acc[8][8];
#pragma unroll
    for (int i = 0; i < 8; i++)
#pragma unroll
        for (int j = 0; j < 8; j++) acc[i][j] = 0.0f;

    for (int k0 = 0; k0 < 128; k0 += 16) {
#pragma unroll
        for (int i = 0; i < 2; i++) {
            int id = tid + i * 256;
            int r = id >> 2, q = id & 3;
            float4 v = *(const float4*)(P + (size_t)r * NN + n0 + k0 + q * 4);
            As[q*4+0][r] = v.x; As[q*4+1][r] = v.y;
            As[q*4+2][r] = v.z; As[q*4+3][r] = v.w;
            float4 u = *(const float4*)(G + (size_t)r * NN + n0 + k0 + q * 4);
            Bs[q*4+0][r] = u.x; Bs[q*4+1][r] = u.y;
            Bs[q*4+2][r] = u.z; Bs[q*4+3][r] = u.w;
        }
        __syncthreads();
#pragma unroll
        for (int kk = 0; kk < 16; kk++) {
            float a[8], bb[8];
#pragma unroll
            for (int i = 0; i < 8; i++) a[i] = As[kk][ty * 8 + i];
#pragma unroll
            for (int j = 0; j < 8; j++) bb[j] = Bs[kk][tx * 8 + j];
#pragma unroll
            for (int i = 0; i < 8; i++)
#pragma unroll
                for (int j = 0; j < 8; j++) acc[i][j] = fmaf(a[i], bb[j], acc[i][j]);
        }
        __syncthreads();
    }

    float* Sp = d_S + (size_t)b * CI * CI;
#pragma unroll
    for (int i = 0; i < 8; i++)
#pragma unroll
        for (int j = 0; j < 8; j++)
            atomicAdd(&Sp[(size_t)(ty * 8 + i) * CI + tx * 8 + j], acc[i][j]);
}

// ---------------------------------------------------------------------------
// K3: M[b,o,a] = (1/N) * sum_ci w_w[o,ci] * S[b,a,ci].  64(o) x 128(a) tiles.
// ---------------------------------------------------------------------------
__global__ __launch_bounds__(256) void k_M(const float* __restrict__ ww)
{
    __shared__ float As[16][68];  // As[k=ci][o]
    __shared__ float Bs[16][132]; // Bs[k=ci][a]

    const int tid = threadIdx.x;
    const int b   = blockIdx.x;
    const int o0  = blockIdx.y * 64;
    const float* Sp = d_S + (size_t)b * CI * CI;
    const int tx = tid & 15, ty = tid >> 4;

    float acc[4][8];
#pragma unroll
    for (int i = 0; i < 4; i++)
#pragma unroll
        for (int j = 0; j < 8; j++) acc[i][j] = 0.0f;

    for (int k0 = 0; k0 < CI; k0 += 16) {
        {
            int o = tid >> 2, q = tid & 3;
            float4 v = *(const float4*)(ww + (size_t)(o0 + o) * CI + k0 + q * 4);
            As[q*4+0][o] = v.x; As[q*4+1][o] = v.y;
            As[q*4+2][o] = v.z; As[q*4+3][o] = v.w;
        }
#pragma unroll
        for (int i = 0; i < 2; i++) {
            int id = tid + i * 256;
            int a = id >> 2, q = id & 3;
            float4 v = *(const float4*)(Sp + (size_t)a * CI + k0 + q * 4);
            Bs[q*4+0][a] = v.x; Bs[q*4+1][a] = v.y;
            Bs[q*4+2][a] = v.z; Bs[q*4+3][a] = v.w;
        }
        __syncthreads();
#pragma unroll
        for (int kk = 0; kk < 16; kk++) {
            float a[4], bb[8];
#pragma unroll
            for (int i = 0; i < 4; i++) a[i] = As[kk][ty * 4 + i];
#pragma unroll
            for (int j = 0; j < 8; j++) bb[j] = Bs[kk][tx * 8 + j];
#pragma unroll
            for (int i = 0; i < 4; i++)
#pragma unroll
                for (int j = 0; j < 8; j++) acc[i][j] = fmaf(a[i], bb[j], acc[i][j]);
        }
        __syncthreads();
    }

    const float invN = 1.0f / NN;
    float* Mp = d_M + (size_t)b * CC * CI;
#pragma unroll
    for (int i = 0; i < 4; i++)
#pragma unroll
        for (int j = 0; j < 8; j++)
            Mp[(size_t)(o0 + ty * 4 + i) * CI + tx * 8 + j] = acc[i][j] * invN;
}

// ---------------------------------------------------------------------------
// K4: wy[b,o,t] = sum_a M[b,o,a] * theta[b,a,t] + w_b[o]; fused BN partial
// sums (sum, sumsq per channel) via warp shfl + atomics.
// ---------------------------------------------------------------------------
__global__ __launch_bounds__(256) void k_wy(const float* __restrict__ wb)
{
    __shared__ float As[32][132]; // As[k][o] = M[o][k]
    __shared__ float Bs[32][128]; // Bs[k][t] = theta[k][t]

    const int tid = threadIdx.x;
    const int b   = blockIdx.z;
    const int o0  = blockIdx.y * 128;
    const int t0  = blockIdx.x * 128;
    const float* Mp = d_M + (size_t)b * CC * CI + (size_t)o0 * CI;
    const float* Th = d_theta + (size_t)b * CI * TT;
    const int tx = tid & 15, ty = tid >> 4;

    float acc[8][8];
#pragma unroll
    for (int i = 0; i < 8; i++)
#pragma unroll
        for (int j = 0; j < 8; j++) acc[i][j] = 0.0f;

    for (int k0 = 0; k0 < CI; k0 += 32) {
#pragma unroll
        for (int i = 0; i < 4; i++) {
            int id = tid + i * 256;
            int o = id >> 3, q = id & 7;
            float4 v = *(const float4*)(Mp + (size_t)o * CI + k0 + q * 4);
            As[q*4+0][o] = v.x; As[q*4+1][o] = v.y;
            As[q*4+2][o] = v.z; As[q*4+3][o] = v.w;
        }
#pragma unroll
        for (int i = 0; i < 4; i++) {
            int id = tid + i * 256;
            int c = id >> 5, qt = id & 31;
            *(float4*)(&Bs[c][qt * 4]) =
                *(const float4*)(Th + (size_t)(k0 + c) * TT + t0 + qt * 4);
        }
        __syncthreads();
#pragma unroll
        for (int kk = 0; kk < 32; kk++) {
            float a[8], bb[8];
#pragma unroll
            for (int i = 0; i < 8; i++) a[i] = As[kk][ty * 8 + i];
#pragma unroll
            for (int j = 0; j < 8; j++) bb[j] = Bs[kk][tx * 8 + j];
#pragma unroll
            for (int i = 0; i < 8; i++)
#pragma unroll
                for (int j = 0; j < 8; j++) acc[i][j] = fmaf(a[i], bb[j], acc[i][j]);
        }
        __syncthreads();
    }

    float* wyp = d_wy + (size_t)b * CC * TT;
#pragma unroll
    for (int i = 0; i < 8; i++) {
        int o = o0 + ty * 8 + i;
        float bz = wb[o];
        float v[8];
        float s = 0.0f, qq = 0.0f;
#pragma unroll
        for (int j = 0; j < 8; j++) {
            v[j] = acc[i][j] + bz;
            s += v[j];
            qq = fmaf(v[j], v[j], qq);
        }
        *(float4*)(wyp + (size_t)o * TT + t0 + tx * 8)     = make_float4(v[0], v[1], v[2], v[3]);
        *(float4*)(wyp + (size_t)o * TT + t0 + tx * 8 + 4) = make_float4(v[4], v[5], v[6], v[7]);
        // reduce over the 16 tx lanes (same half-warp)
#pragma unroll
        for (int off = 8; off > 0; off >>= 1) {
            s  += __shfl_xor_sync(0xffffffffu, s,  off);
            qq += __shfl_xor_sync(0xffffffffu, qq, off);
        }
        if (tx == 0) {
            atomicAdd(&d_sum[o], s);
            atomicAdd(&d_sumsq[o], qq);
        }
    }
}

// ---------------------------------------------------------------------------
// K5: finalize BN statistics into scale/shift.
// ---------------------------------------------------------------------------
__global__ void k_stats(const float* __restrict__ gamma, const float* __restrict__ beta)
{
    int o = threadIdx.x;
    if (o < CC) {
        float mean = d_sum[o]   * (1.0f / BNT);
        float var  = d_sumsq[o] * (1.0f / BNT) - mean * mean;
        float sc   = gamma[o] * rsqrtf(var + 1e-5f);
        d_scale[o] = sc;
        d_shift[o] = beta[o] - mean * sc;
    }
}

// ---------------------------------------------------------------------------
// K6: out = scale[o]*wy + shift[o] + x  (elementwise, float4)
// ---------------------------------------------------------------------------
__global__ __launch_bounds__(256) void k_out(const float* __restrict__ x,
                                             float* __restrict__ out)
{
    size_t i4 = (size_t)blockIdx.x * 256 + threadIdx.x;   // float4 index
    int o = (int)((i4 >> 11) & 255);                      // (i4*4 / T) % C
    float sc = d_scale[o], sh = d_shift[o];
    float4 w  = *((const float4*)d_wy + i4);
    float4 xv = *((const float4*)x + i4);
    float4 r;
    r.x = fmaf(sc, w.x, sh) + xv.x;
    r.y = fmaf(sc, w.y, sh) + xv.y;
    r.z = fmaf(sc, w.z, sh) + xv.z;
    r.w = fmaf(sc, w.w, sh) + xv.w;
    ((float4*)out)[i4] = r;
}

// ---------------------------------------------------------------------------
extern "C" void kernel_launch(void* const* d_in, const int* in_sizes, int n_in,
                              void* d_out, int out_size)
{
    const float* x     = (const float*)d_in[0];
    const float* tw    = (const float*)d_in[1];
    const float* tb    = (const float*)d_in[2];
    const float* pw    = (const float*)d_in[3];
    const float* pb    = (const float*)d_in[4];
    const float* gw    = (const float*)d_in[5];
    const float* gb    = (const float*)d_in[6];
    const float* ww    = (const float*)d_in[7];
    const float* wb    = (const float*)d_in[8];
    const float* gamma = (const float*)d_in[9];
    const float* beta  = (const float*)d_in[10];
    float* out = (float*)d_out;

    k_init<<<256, 256>>>();
    k_conv<<<dim3(TT / 128, 3, BB), 256>>>(x, tw, tb, pw, pb, gw, gb);
    k_S<<<dim3(32, BB), 256>>>();
    k_M<<<dim3(BB, 4), 256>>>(ww);
    k_wy<<<dim3(TT / 128, 2, BB), 256>>>(wb);
    k_stats<<<1, 256>>>(gamma, beta);
    k_out<<<8192, 256>>>(x, out);
}

// round 2
// speedup vs baseline: 1.0206x; 1.0206x over previous
#include <cuda_runtime.h>

#define BB 4
#define CC 256
#define CI 128
#define TT 8192
#define NN 4096
#define BNT (BB*TT)

typedef unsigned long long u64;

// Scratch (device globals; no allocation allowed)
__device__ float d_theta[BB*CI*TT];   // 16 MB
__device__ float d_phi[BB*CI*NN];     // 8 MB
__device__ float d_g[BB*CI*NN];       // 8 MB
__device__ float d_S[BB*CI*CI];       // 256 KB
__device__ float d_M[BB*CC*CI];       // 512 KB
__device__ float d_wy[BB*CC*TT];      // 32 MB
__device__ float d_sum[CC];
__device__ float d_sumsq[CC];
__device__ float d_scale[CC];
__device__ float d_shift[CC];

// packed-f32x2 helpers -------------------------------------------------------
__device__ __forceinline__ void ffma2(u64& d, u64 a, u64 b) {
    asm("fma.rn.f32x2 %0, %1, %2, %0;" : "+l"(d) : "l"(a), "l"(b));
}
__device__ __forceinline__ u64 dup2(float a) {
    u64 r;
    asm("mov.b64 %0, {%1, %1};" : "=l"(r) : "f"(a));
    return r;
}
__device__ __forceinline__ float lo32(u64 v) { return __uint_as_float((unsigned)v); }
__device__ __forceinline__ float hi32(u64 v) { return __uint_as_float((unsigned)(v >> 32)); }

// ---------------------------------------------------------------------------
// K0: zero accumulators (sum, sumsq). Re-run each launch for determinism.
// ---------------------------------------------------------------------------
__global__ void k_init() {
    int i = blockIdx.x * blockDim.x + threadIdx.x;
    if (i < BB*CI*CI) d_S[i] = 0.0f;
    if (i < CC) { d_sum[i] = 0.0f; d_sumsq[i] = 0.0f; }
}

// ---------------------------------------------------------------------------
// K1: fused 1x1 convs, f32x2 FMA. out(128 x 128t) = W(128x256) @ x[b].
// blockIdx.y selects theta/phi/g. phi/g maxpooled (stride-2) in registers.
// ---------------------------------------------------------------------------
__global__ __launch_bounds__(256) void k_conv(
    const float* __restrict__ x,
    const float* __restrict__ Wt, const float* __restrict__ bt,
    const float* __restrict__ Wp, const float* __restrict__ bp,
    const float* __restrict__ Wg, const float* __restrict__ bg)
{
    __shared__ float As[32][132];  // As[k][o] = W[o][k0+k]
    __shared__ float Bs[32][128];  // Bs[k][t]

    const int tid = threadIdx.x;
    const int b   = blockIdx.z;
    const int w   = blockIdx.y;
    const int t0  = blockIdx.x * 128;

    const float* W    = (w == 0) ? Wt : ((w == 1) ? Wp : Wg);
    const float* bias = (w == 0) ? bt : ((w == 1) ? bp : bg);
    const float* xb   = x + (size_t)b * CC * TT;

    const int tx = tid & 15;
    const int ty = tid >> 4;

    u64 acc[8][4];
#pragma unroll
    for (int i = 0; i < 8; i++)
#pragma unroll
        for (int j = 0; j < 4; j++) acc[i][j] = 0ull;

    for (int k0 = 0; k0 < CC; k0 += 32) {
#pragma unroll
        for (int i = 0; i < 4; i++) {
            int id = tid + i * 256;
            int o = id >> 3, q = id & 7;
            float4 v = *(const float4*)(W + (size_t)o * CC + k0 + q * 4);
            As[q*4+0][o] = v.x; As[q*4+1][o] = v.y;
            As[q*4+2][o] = v.z; As[q*4+3][o] = v.w;
        }
#pragma unroll
        for (int i = 0; i < 4; i++) {
            int id = tid + i * 256;
            int c = id >> 5, qt = id & 31;
            *(float4*)(&Bs[c][qt * 4]) =
                *(const float4*)(xb + (size_t)(k0 + c) * TT + t0 + qt * 4);
        }
        __syncthreads();
#pragma unroll
        for (int kk = 0; kk < 32; kk++) {
            float a[8];
#pragma unroll
            for (int i = 0; i < 8; i++) a[i] = As[kk][ty * 8 + i];
            const u64* Bp = (const u64*)(&Bs[kk][tx * 8]);
            u64 bp[4];
#pragma unroll
            for (int j = 0; j < 4; j++) bp[j] = Bp[j];
#pragma unroll
            for (int i = 0; i < 8; i++) {
                u64 ad = dup2(a[i]);
#pragma unroll
                for (int j = 0; j < 4; j++) ffma2(acc[i][j], ad, bp[j]);
            }
        }
        __syncthreads();
    }

    if (w == 0) {
        float* dst = d_theta + (size_t)b * CI * TT;
#pragma unroll
        for (int i = 0; i < 8; i++) {
            int o = ty * 8 + i;
            float bz = bias[o];
            float4 v0 = make_float4(lo32(acc[i][0])+bz, hi32(acc[i][0])+bz,
                                    lo32(acc[i][1])+bz, hi32(acc[i][1])+bz);
            float4 v1 = make_float4(lo32(acc[i][2])+bz, hi32(acc[i][2])+bz,
                                    lo32(acc[i][3])+bz, hi32(acc[i][3])+bz);
            *(float4*)(dst + (size_t)o * TT + t0 + tx * 8)     = v0;
            *(float4*)(dst + (size_t)o * TT + t0 + tx * 8 + 4) = v1;
        }
    } else {
        float* dst = ((w == 1) ? d_phi : d_g) + (size_t)b * CI * NN;
        int n0 = (t0 + tx * 8) >> 1;
#pragma unroll
        for (int i = 0; i < 8; i++) {
            int o = ty * 8 + i;
            float bz = bias[o];
            float4 v;
            v.x = fmaxf(lo32(acc[i][0]), hi32(acc[i][0])) + bz;
            v.y = fmaxf(lo32(acc[i][1]), hi32(acc[i][1])) + bz;
            v.z = fmaxf(lo32(acc[i][2]), hi32(acc[i][2])) + bz;
            v.w = fmaxf(lo32(acc[i][3]), hi32(acc[i][3])) + bz;
            *(float4*)(dst + (size_t)o * NN + n0) = v;
        }
    }
}

// ---------------------------------------------------------------------------
// K2: S[b,a,ci] = sum_n phi[b,a,n] * g[b,ci,n].  Split-K over n, atomics.
// ---------------------------------------------------------------------------
__global__ __launch_bounds__(256) void k_S()
{
    __shared__ float As[16][132]; // As[kn][a]
    __shared__ float Bs[16][132]; // Bs[kn][ci]

    const int tid = threadIdx.x;
    const int b   = blockIdx.y;
    const int n0  = blockIdx.x * 128;
    const float* P = d_phi + (size_t)b * CI * NN;
    const float* G = d_g   + (size_t)b * CI * NN;
    const int tx = tid & 15, ty = tid >> 4;

    u64 acc[8][4];
#pragma unroll
    for (int i = 0; i < 8; i++)
#pragma unroll
        for (int j = 0; j < 4; j++) acc[i][j] = 0ull;

    for (int k0 = 0; k0 < 128; k0 += 16) {
#pragma unroll
        for (int i = 0; i < 2; i++) {
            int id = tid + i * 256;
            int r = id >> 2, q = id & 3;
            float4 v = *(const float4*)(P + (size_t)r * NN + n0 + k0 + q * 4);
            As[q*4+0][r] = v.x; As[q*4+1][r] = v.y;
            As[q*4+2][r] = v.z; As[q*4+3][r] = v.w;
            float4 u = *(const float4*)(G + (size_t)r * NN + n0 + k0 + q * 4);
            Bs[q*4+0][r] = u.x; Bs[q*4+1][r] = u.y;
            Bs[q*4+2][r] = u.z; Bs[q*4+3][r] = u.w;
        }
        __syncthreads();
#pragma unroll
        for (int kk = 0; kk < 16; kk++) {
            float a[8];
#pragma unroll
            for (int i = 0; i < 8; i++) a[i] = As[kk][ty * 8 + i];
            const u64* Bp = (const u64*)(&Bs[kk][tx * 8]);
            u64 bp[4];
#pragma unroll
            for (int j = 0; j < 4; j++) bp[j] = Bp[j];
#pragma unroll
            for (int i = 0; i < 8; i++) {
                u64 ad = dup2(a[i]);
#pragma unroll
                for (int j = 0; j < 4; j++) ffma2(acc[i][j], ad, bp[j]);
            }
        }
        __syncthreads();
    }

    float* Sp = d_S + (size_t)b * CI * CI;
#pragma unroll
    for (int i = 0; i < 8; i++)
#pragma unroll
        for (int j = 0; j < 4; j++) {
            atomicAdd(&Sp[(size_t)(ty * 8 + i) * CI + tx * 8 + 2*j],     lo32(acc[i][j]));
            atomicAdd(&Sp[(size_t)(ty * 8 + i) * CI + tx * 8 + 2*j + 1], hi32(acc[i][j]));
        }
}

// ---------------------------------------------------------------------------
// K3: M[b,o,a] = (1/N) * sum_ci w_w[o,ci] * S[b,a,ci].
// One thread per output element; everything L2-resident.
// ---------------------------------------------------------------------------
__global__ __launch_bounds__(256) void k_M(const float* __restrict__ ww)
{
    int idx = blockIdx.x * 256 + threadIdx.x;   // 0 .. BB*CC*CI-1
    int a =  idx & (CI - 1);
    int o = (idx >> 7) & (CC - 1);
    int b =  idx >> 15;
    const float4* wr = (const float4*)(ww + (size_t)o * CI);
    const float4* sr = (const float4*)(d_S + (size_t)b * CI * CI + (size_t)a * CI);
    float s0 = 0.f, s1 = 0.f, s2 = 0.f, s3 = 0.f;
#pragma unroll
    for (int k = 0; k < CI / 4; k++) {
        float4 wv = wr[k], sv = sr[k];
        s0 = fmaf(wv.x, sv.x, s0);
        s1 = fmaf(wv.y, sv.y, s1);
        s2 = fmaf(wv.z, sv.z, s2);
        s3 = fmaf(wv.w, sv.w, s3);
    }
    d_M[(size_t)b * CC * CI + (size_t)o * CI + a] =
        ((s0 + s1) + (s2 + s3)) * (1.0f / NN);
}

// ---------------------------------------------------------------------------
// K4: wy[b,o,t] = sum_a M[b,o,a] * theta[b,a,t] + w_b[o]; fused BN partials.
// ---------------------------------------------------------------------------
__global__ __launch_bounds__(256) void k_wy(const float* __restrict__ wb)
{
    __shared__ float As[32][132]; // As[k][o] = M[o][k]
    __shared__ float Bs[32][128]; // Bs[k][t]

    const int tid = threadIdx.x;
    const int b   = blockIdx.z;
    const int o0  = blockIdx.y * 128;
    const int t0  = blockIdx.x * 128;
    const float* Mp = d_M + (size_t)b * CC * CI + (size_t)o0 * CI;
    const float* Th = d_theta + (size_t)b * CI * TT;
    const int tx = tid & 15, ty = tid >> 4;

    u64 acc[8][4];
#pragma unroll
    for (int i = 0; i < 8; i++)
#pragma unroll
        for (int j = 0; j < 4; j++) acc[i][j] = 0ull;

    for (int k0 = 0; k0 < CI; k0 += 32) {
#pragma unroll
        for (int i = 0; i < 4; i++) {
            int id = tid + i * 256;
            int o = id >> 3, q = id & 7;
            float4 v = *(const float4*)(Mp + (size_t)o * CI + k0 + q * 4);
            As[q*4+0][o] = v.x; As[q*4+1][o] = v.y;
            As[q*4+2][o] = v.z; As[q*4+3][o] = v.w;
        }
#pragma unroll
        for (int i = 0; i < 4; i++) {
            int id = tid + i * 256;
            int c = id >> 5, qt = id & 31;
            *(float4*)(&Bs[c][qt * 4]) =
                *(const float4*)(Th + (size_t)(k0 + c) * TT + t0 + qt * 4);
        }
        __syncthreads();
#pragma unroll
        for (int kk = 0; kk < 32; kk++) {
            float a[8];
#pragma unroll
            for (int i = 0; i < 8; i++) a[i] = As[kk][ty * 8 + i];
            const u64* Bp = (const u64*)(&Bs[kk][tx * 8]);
            u64 bp[4];
#pragma unroll
            for (int j = 0; j < 4; j++) bp[j] = Bp[j];
#pragma unroll
            for (int i = 0; i < 8; i++) {
                u64 ad = dup2(a[i]);
#pragma unroll
                for (int j = 0; j < 4; j++) ffma2(acc[i][j], ad, bp[j]);
            }
        }
        __syncthreads();
    }

    float* wyp = d_wy + (size_t)b * CC * TT;
#pragma unroll
    for (int i = 0; i < 8; i++) {
        int o = o0 + ty * 8 + i;
        float bz = wb[o];
        float v[8];
        v[0] = lo32(acc[i][0]) + bz; v[1] = hi32(acc[i][0]) + bz;
        v[2] = lo32(acc[i][1]) + bz; v[3] = hi32(acc[i][1]) + bz;
        v[4] = lo32(acc[i][2]) + bz; v[5] = hi32(acc[i][2]) + bz;
        v[6] = lo32(acc[i][3]) + bz; v[7] = hi32(acc[i][3]) + bz;
        float s = 0.0f, qq = 0.0f;
#pragma unroll
        for (int j = 0; j < 8; j++) { s += v[j]; qq = fmaf(v[j], v[j], qq); }
        *(float4*)(wyp + (size_t)o * TT + t0 + tx * 8)     = make_float4(v[0], v[1], v[2], v[3]);
        *(float4*)(wyp + (size_t)o * TT + t0 + tx * 8 + 4) = make_float4(v[4], v[5], v[6], v[7]);
#pragma unroll
        for (int off = 8; off > 0; off >>= 1) {
            s  += __shfl_xor_sync(0xffffffffu, s,  off);
            qq += __shfl_xor_sync(0xffffffffu, qq, off);
        }
        if (tx == 0) {
            atomicAdd(&d_sum[o], s);
            atomicAdd(&d_sumsq[o], qq);
        }
    }
}

// ---------------------------------------------------------------------------
// K5: finalize BN statistics into scale/shift.
// ---------------------------------------------------------------------------
__global__ void k_stats(const float* __restrict__ gamma, const float* __restrict__ beta)
{
    int o = threadIdx.x;
    if (o < CC) {
        float mean = d_sum[o]   * (1.0f / BNT);
        float var  = d_sumsq[o] * (1.0f / BNT) - mean * mean;
        float sc   = gamma[o] * rsqrtf(var + 1e-5f);
        d_scale[o] = sc;
        d_shift[o] = beta[o] - mean * sc;
    }
}

// ---------------------------------------------------------------------------
// K6: out = scale[o]*wy + shift[o] + x  (elementwise, float4)
// ---------------------------------------------------------------------------
__global__ __launch_bounds__(256) void k_out(const float* __restrict__ x,
                                             float* __restrict__ out)
{
    size_t i4 = (size_t)blockIdx.x * 256 + threadIdx.x;
    int o = (int)((i4 >> 11) & 255);
    float sc = d_scale[o], sh = d_shift[o];
    float4 w  = *((const float4*)d_wy + i4);
    float4 xv = *((const float4*)x + i4);
    float4 r;
    r.x = fmaf(sc, w.x, sh) + xv.x;
    r.y = fmaf(sc, w.y, sh) + xv.y;
    r.z = fmaf(sc, w.z, sh) + xv.z;
    r.w = fmaf(sc, w.w, sh) + xv.w;
    ((float4*)out)[i4] = r;
}

// ---------------------------------------------------------------------------
extern "C" void kernel_launch(void* const* d_in, const int* in_sizes, int n_in,
                              void* d_out, int out_size)
{
    const float* x     = (const float*)d_in[0];
    const float* tw    = (const float*)d_in[1];
    const float* tb    = (const float*)d_in[2];
    const float* pw    = (const float*)d_in[3];
    const float* pb    = (const float*)d_in[4];
    const float* gw    = (const float*)d_in[5];
    const float* gb    = (const float*)d_in[6];
    const float* ww    = (const float*)d_in[7];
    const float* wb    = (const float*)d_in[8];
    const float* gamma = (const float*)d_in[9];
    const float* beta  = (const float*)d_in[10];
    float* out = (float*)d_out;

    k_init<<<256, 256>>>();
    k_conv<<<dim3(TT / 128, 3, BB), 256>>>(x, tw, tb, pw, pb, gw, gb);
    k_S<<<dim3(32, BB), 256>>>();
    k_M<<<512, 256>>>(ww);
    k_wy<<<dim3(TT / 128, 2, BB), 256>>>(wb);
    k_stats<<<1, 256>>>(gamma, beta);
    k_out<<<8192, 256>>>(x, out);
}

// round 5
// speedup vs baseline: 1.7334x; 1.6985x over previous
#include <cuda_runtime.h>
#include <cstdint>

#define BB 4
#define CC 256
#define CI 128
#define TT 8192
#define NN 4096
#define BNT (BB*TT)

typedef unsigned long long u64;

// Scratch (device globals; no allocation allowed)
__device__ float d_theta[BB*CI*TT];   // 16 MB
__device__ float d_phi[BB*CI*NN];     // 8 MB
__device__ float d_g[BB*CI*NN];       // 8 MB
__device__ float d_S[BB*CI*CI];       // 256 KB
__device__ float d_M[BB*CC*CI];       // 512 KB
__device__ float d_wy[BB*CC*TT];      // 32 MB
__device__ float d_sum[CC];
__device__ float d_sumsq[CC];
__device__ float d_scale[CC];
__device__ float d_shift[CC];

// ---------------- packed-f32x2 helpers (k_S) --------------------------------
__device__ __forceinline__ void ffma2(u64& d, u64 a, u64 b) {
    asm("fma.rn.f32x2 %0, %1, %2, %0;" : "+l"(d) : "l"(a), "l"(b));
}
__device__ __forceinline__ u64 dup2(float a) {
    u64 r; asm("mov.b64 %0, {%1, %1};" : "=l"(r) : "f"(a)); return r;
}
__device__ __forceinline__ float lo32(u64 v) { return __uint_as_float((unsigned)v); }
__device__ __forceinline__ float hi32(u64 v) { return __uint_as_float((unsigned)(v >> 32)); }

// ---------------- tf32 mma.sync helpers (base PTX, works on sm_103) ---------
__device__ __forceinline__ uint32_t cvt_tf32(float v) {
    uint32_t t; asm("cvt.rn.tf32.f32 %0, %1;" : "=r"(t) : "f"(v)); return t;
}
__device__ __forceinline__ void mma_tf32(float* d, const uint32_t* a, const uint32_t* b) {
    asm("mma.sync.aligned.m16n8k8.row.col.f32.tf32.tf32.f32 "
        "{%0,%1,%2,%3}, {%4,%5,%6,%7}, {%8,%9}, {%0,%1,%2,%3};"
        : "+f"(d[0]), "+f"(d[1]), "+f"(d[2]), "+f"(d[3])
        : "r"(a[0]), "r"(a[1]), "r"(a[2]), "r"(a[3]), "r"(b[0]), "r"(b[1]));
}

// SMEM geometry for the HMMA kernels (dynamic smem):
//   Af: fragment-major A, 8 m-tiles x 8 k-steps x 4 j x 32 lanes = 8192 u32 (32 KB)
//   Bs: [64 k][128 t + pad4] = 64*132 u32 (33792 B)
#define AF_U32   8192
#define PADB     132
#define SMEM_HMMA (AF_U32*4 + 64*PADB*4)   // 66560 B

// Stage A chunk (128 rows x 64 k) from row-major W (ld=ldw) into frag-major Af.
__device__ __forceinline__ void stageA_frag(const float* __restrict__ W, int ldw,
                                            int kc, uint32_t* Af, int tid) {
#pragma unroll
    for (int i = 0; i < 8; i++) {
        int fid = i * 256 + tid;          // 0..2047 float4s
        int o = fid >> 4;                 // 0..127
        int q = fid & 15;                 // k float4 index
        float4 v = *(const float4*)(W + (size_t)o * ldw + kc * 64 + 4 * q);
        int mt = o >> 4, r = o & 15;
        int ks = q >> 1;
        int j  = ((q & 1) << 1) | (r >> 3);
        int l0 = (r & 7) << 2;
        uint32_t* dst = Af + (((mt * 8 + ks) * 4 + j) * 32 + l0);
        *(uint4*)dst = make_uint4(cvt_tf32(v.x), cvt_tf32(v.y), cvt_tf32(v.z), cvt_tf32(v.w));
    }
}

// Stage B chunk (64 k x 128 t) from row-major src (ld=lds) into [k][t] padded.
__device__ __forceinline__ void stageB(const float* __restrict__ src, int lds,
                                       int t0, int kc, uint32_t* Bs, int tid) {
#pragma unroll
    for (int i = 0; i < 8; i++) {
        int fid = i * 256 + tid;          // 0..2047
        int k  = fid >> 5;                // 0..63
        int t4 = (fid & 31) << 2;
        float4 v = *(const float4*)(src + (size_t)(kc * 64 + k) * lds + t0 + t4);
        uint32_t* d = Bs + k * PADB + t4;
        *(uint4*)d = make_uint4(cvt_tf32(v.x), cvt_tf32(v.y), cvt_tf32(v.z), cvt_tf32(v.w));
    }
}

// ---------------------------------------------------------------------------
// K0: zero accumulators.
// ---------------------------------------------------------------------------
__global__ void k_init() {
    int i = blockIdx.x * blockDim.x + threadIdx.x;
    if (i < BB*CI*CI) d_S[i] = 0.0f;
    if (i < CC) { d_sum[i] = 0.0f; d_sumsq[i] = 0.0f; }
}

// ---------------------------------------------------------------------------
// K1: fused 1x1 convs via tf32 mma.sync. Block: 128 o x 128 t, K=256.
// 8 warps in 4(o) x 2(t); warp tile 32o x 64t. phi/g maxpooled in epilogue.
// ---------------------------------------------------------------------------
__global__ __launch_bounds__(256) void k_conv_hmma(
    const float* __restrict__ x,
    const float* __restrict__ Wt, const float* __restrict__ bt,
    const float* __restrict__ Wp, const float* __restrict__ bp,
    const float* __restrict__ Wg, const float* __restrict__ bg)
{
    extern __shared__ uint32_t smem[];
    uint32_t* Af = smem;
    uint32_t* Bs = smem + AF_U32;

    const int tid = threadIdx.x;
    const int warp = tid >> 5, lane = tid & 31;
    const int wo = warp >> 1, wt = warp & 1;
    const int b  = blockIdx.z;
    const int w  = blockIdx.y;
    const int t0 = blockIdx.x * 128;

    const float* W    = (w == 0) ? Wt : ((w == 1) ? Wp : Wg);
    const float* bias = (w == 0) ? bt : ((w == 1) ? bp : bg);
    const float* xb   = x + (size_t)b * CC * TT;

    float acc[2][8][4];
#pragma unroll
    for (int mi = 0; mi < 2; mi++)
#pragma unroll
        for (int nt = 0; nt < 8; nt++)
#pragma unroll
            for (int j = 0; j < 4; j++) acc[mi][nt][j] = 0.0f;

    const int lq = lane & 3, lr = lane >> 2;

    for (int kc = 0; kc < 4; kc++) {
        stageA_frag(W, CC, kc, Af, tid);
        stageB(xb, TT, t0, kc, Bs, tid);
        __syncthreads();
#pragma unroll
        for (int ks = 0; ks < 8; ks++) {
            uint32_t a[2][4], bf[8][2];
#pragma unroll
            for (int mi = 0; mi < 2; mi++) {
                int mt = wo * 2 + mi;
#pragma unroll
                for (int j = 0; j < 4; j++)
                    a[mi][j] = Af[((mt * 8 + ks) * 4 + j) * 32 + lane];
            }
            int k0 = ks * 8;
            int tb = wt * 64 + lr;
#pragma unroll
            for (int nt = 0; nt < 8; nt++) {
                bf[nt][0] = Bs[(k0 + lq) * PADB + tb + nt * 8];
                bf[nt][1] = Bs[(k0 + 4 + lq) * PADB + tb + nt * 8];
            }
#pragma unroll
            for (int mi = 0; mi < 2; mi++)
#pragma unroll
                for (int nt = 0; nt < 8; nt++)
                    mma_tf32(acc[mi][nt], a[mi], bf[nt]);
        }
        __syncthreads();
    }

    // Epilogue. D frag: d0=D[lr][2lq], d1=D[lr][2lq+1], d2=D[lr+8][2lq], d3=D[lr+8][2lq+1]
    if (w == 0) {
        float* dst = d_theta + (size_t)b * CI * TT;
#pragma unroll
        for (int mi = 0; mi < 2; mi++) {
            int o1 = wo * 32 + mi * 16 + lr;
            int o2 = o1 + 8;
            float bz1 = bias[o1], bz2 = bias[o2];
#pragma unroll
            for (int nt = 0; nt < 8; nt++) {
                int t = t0 + wt * 64 + nt * 8 + 2 * lq;
                *(float2*)(dst + (size_t)o1 * TT + t) =
                    make_float2(acc[mi][nt][0] + bz1, acc[mi][nt][1] + bz1);
                *(float2*)(dst + (size_t)o2 * TT + t) =
                    make_float2(acc[mi][nt][2] + bz2, acc[mi][nt][3] + bz2);
            }
        }
    } else {
        float* dst = ((w == 1) ? d_phi : d_g) + (size_t)b * CI * NN;
#pragma unroll
        for (int mi = 0; mi < 2; mi++) {
            int o1 = wo * 32 + mi * 16 + lr;
            int o2 = o1 + 8;
            float bz1 = bias[o1], bz2 = bias[o2];
#pragma unroll
            for (int nt = 0; nt < 8; nt++) {
                int n = (t0 >> 1) + wt * 32 + nt * 4 + lq;
                dst[(size_t)o1 * NN + n] = fmaxf(acc[mi][nt][0], acc[mi][nt][1]) + bz1;
                dst[(size_t)o2 * NN + n] = fmaxf(acc[mi][nt][2], acc[mi][nt][3]) + bz2;
            }
        }
    }
}

// ---------------------------------------------------------------------------
// K2: S[b,a,ci] = sum_n phi[b,a,n]*g[b,ci,n]. SIMT split-K + atomics.
// ---------------------------------------------------------------------------
__global__ __launch_bounds__(256) void k_S()
{
    __shared__ float As[16][132];
    __shared__ float Bss[16][132];

    const int tid = threadIdx.x;
    const int b   = blockIdx.y;
    const int n0  = blockIdx.x * 128;
    const float* P = d_phi + (size_t)b * CI * NN;
    const float* G = d_g   + (size_t)b * CI * NN;
    const int tx = tid & 15, ty = tid >> 4;

    u64 acc[8][4];
#pragma unroll
    for (int i = 0; i < 8; i++)
#pragma unroll
        for (int j = 0; j < 4; j++) acc[i][j] = 0ull;

    for (int k0 = 0; k0 < 128; k0 += 16) {
#pragma unroll
        for (int i = 0; i < 2; i++) {
            int id = tid + i * 256;
            int r = id >> 2, q = id & 3;
            float4 v = *(const float4*)(P + (size_t)r * NN + n0 + k0 + q * 4);
            As[q*4+0][r] = v.x; As[q*4+1][r] = v.y;
            As[q*4+2][r] = v.z; As[q*4+3][r] = v.w;
            float4 u = *(const float4*)(G + (size_t)r * NN + n0 + k0 + q * 4);
            Bss[q*4+0][r] = u.x; Bss[q*4+1][r] = u.y;
            Bss[q*4+2][r] = u.z; Bss[q*4+3][r] = u.w;
        }
        __syncthreads();
#pragma unroll
        for (int kk = 0; kk < 16; kk++) {
            float a[8];
#pragma unroll
            for (int i = 0; i < 8; i++) a[i] = As[kk][ty * 8 + i];
            const u64* Bp = (const u64*)(&Bss[kk][tx * 8]);
            u64 bp[4];
#pragma unroll
            for (int j = 0; j < 4; j++) bp[j] = Bp[j];
#pragma unroll
            for (int i = 0; i < 8; i++) {
                u64 ad = dup2(a[i]);
#pragma unroll
                for (int j = 0; j < 4; j++) ffma2(acc[i][j], ad, bp[j]);
            }
        }
        __syncthreads();
    }

    float* Sp = d_S + (size_t)b * CI * CI;
#pragma unroll
    for (int i = 0; i < 8; i++)
#pragma unroll
        for (int j = 0; j < 4; j++) {
            atomicAdd(&Sp[(size_t)(ty * 8 + i) * CI + tx * 8 + 2*j],     lo32(acc[i][j]));
            atomicAdd(&Sp[(size_t)(ty * 8 + i) * CI + tx * 8 + 2*j + 1], hi32(acc[i][j]));
        }
}

// ---------------------------------------------------------------------------
// K3: M[b,o,a] = (1/N) * sum_k w_w[o,k] * S[b,a,k]. SMEM-staged small GEMM.
// Grid: 128 blocks = b(4) x o-tile(8, 32 rows) x a-tile(4, 32 rows).
// ---------------------------------------------------------------------------
__global__ __launch_bounds__(256) void k_M2(const float* __restrict__ ww)
{
    __shared__ float ws[32][129];
    __shared__ float ss[32][129];

    const int tid = threadIdx.x;
    const int b  = blockIdx.x >> 5;
    const int ob = (blockIdx.x >> 2) & 7;
    const int ab = blockIdx.x & 3;

    // stage w tile (32 o x 128 k) AND S tile (32 a x 128 k): 1024 float4 each
#pragma unroll
    for (int i = 0; i < 4; i++) {
        int fid = i * 256 + tid;
        int r = fid >> 5, c4 = fid & 31;
        float4 v = *(const float4*)(ww + (size_t)(ob * 32 + r) * CI + 4 * c4);
        ws[r][4*c4+0] = v.x; ws[r][4*c4+1] = v.y; ws[r][4*c4+2] = v.z; ws[r][4*c4+3] = v.w;
        float4 u = *(const float4*)(d_S + (size_t)b * CI * CI + (size_t)(ab * 32 + r) * CI + 4 * c4);
        ss[r][4*c4+0] = u.x; ss[r][4*c4+1] = u.y; ss[r][4*c4+2] = u.z; ss[r][4*c4+3] = u.w;
    }
    __syncthreads();

    const int ty = tid >> 3;
    const int tx = tid & 7;
    float acc[4] = {0.f, 0.f, 0.f, 0.f};
#pragma unroll
    for (int k = 0; k < CI; k++) {
        float wv = ws[ty][k];
#pragma unroll
        for (int j = 0; j < 4; j++) acc[j] = fmaf(wv, ss[4*tx+j][k], acc[j]);
    }
    const float invN = 1.0f / NN;
    float* Mp = d_M + (size_t)b * CC * CI + (size_t)(ob * 32 + ty) * CI + ab * 32 + 4 * tx;
#pragma unroll
    for (int j = 0; j < 4; j++) Mp[j] = acc[j] * invN;
}

// ---------------------------------------------------------------------------
// K4: wy = M @ theta + w_b via tf32 mma.sync; fused BN partial sums.
// Block: 128 o x 128 t, K=128.
// ---------------------------------------------------------------------------
__global__ __launch_bounds__(256) void k_wy_hmma(const float* __restrict__ wb)
{
    extern __shared__ uint32_t smem[];
    uint32_t* Af = smem;
    uint32_t* Bs = smem + AF_U32;

    const int tid = threadIdx.x;
    const int warp = tid >> 5, lane = tid & 31;
    const int wo = warp >> 1, wt = warp & 1;
    const int b  = blockIdx.z;
    const int o0 = blockIdx.y * 128;
    const int t0 = blockIdx.x * 128;

    const float* Mp = d_M + (size_t)b * CC * CI + (size_t)o0 * CI;
    const float* Th = d_theta + (size_t)b * CI * TT;

    float acc[2][8][4];
#pragma unroll
    for (int mi = 0; mi < 2; mi++)
#pragma unroll
        for (int nt = 0; nt < 8; nt++)
#pragma unroll
            for (int j = 0; j < 4; j++) acc[mi][nt][j] = 0.0f;

    const int lq = lane & 3, lr = lane >> 2;

    for (int kc = 0; kc < 2; kc++) {
        stageA_frag(Mp, CI, kc, Af, tid);
        stageB(Th, TT, t0, kc, Bs, tid);
        __syncthreads();
#pragma unroll
        for (int ks = 0; ks < 8; ks++) {
            uint32_t a[2][4], bf[8][2];
#pragma unroll
            for (int mi = 0; mi < 2; mi++) {
                int mt = wo * 2 + mi;
#pragma unroll
                for (int j = 0; j < 4; j++)
                    a[mi][j] = Af[((mt * 8 + ks) * 4 + j) * 32 + lane];
            }
            int k0 = ks * 8;
            int tb = wt * 64 + lr;
#pragma unroll
            for (int nt = 0; nt < 8; nt++) {
                bf[nt][0] = Bs[(k0 + lq) * PADB + tb + nt * 8];
                bf[nt][1] = Bs[(k0 + 4 + lq) * PADB + tb + nt * 8];
            }
#pragma unroll
            for (int mi = 0; mi < 2; mi++)
#pragma unroll
                for (int nt = 0; nt < 8; nt++)
                    mma_tf32(acc[mi][nt], a[mi], bf[nt]);
        }
        __syncthreads();
    }

    float* wyp = d_wy + (size_t)b * CC * TT;
#pragma unroll
    for (int mi = 0; mi < 2; mi++) {
        int o1 = o0 + wo * 32 + mi * 16 + lr;
        int o2 = o1 + 8;
        float bz1 = wb[o1], bz2 = wb[o2];
        float s1 = 0.f, q1 = 0.f, s2 = 0.f, q2 = 0.f;
#pragma unroll
        for (int nt = 0; nt < 8; nt++) {
            int t = t0 + wt * 64 + nt * 8 + 2 * lq;
            float v0 = acc[mi][nt][0] + bz1, v1 = acc[mi][nt][1] + bz1;
            float v2 = acc[mi][nt][2] + bz2, v3 = acc[mi][nt][3] + bz2;
            s1 += v0 + v1; q1 = fmaf(v0, v0, q1); q1 = fmaf(v1, v1, q1);
            s2 += v2 + v3; q2 = fmaf(v2, v2, q2); q2 = fmaf(v3, v3, q2);
            *(float2*)(wyp + (size_t)o1 * TT + t) = make_float2(v0, v1);
            *(float2*)(wyp + (size_t)o2 * TT + t) = make_float2(v2, v3);
        }
        // reduce over the 4 lanes of the quad (same lr, lq = 0..3)
#pragma unroll
        for (int off = 1; off < 4; off <<= 1) {
            s1 += __shfl_xor_sync(0xffffffffu, s1, off);
            q1 += __shfl_xor_sync(0xffffffffu, q1, off);
            s2 += __shfl_xor_sync(0xffffffffu, s2, off);
            q2 += __shfl_xor_sync(0xffffffffu, q2, off);
        }
        if (lq == 0) {
            atomicAdd(&d_sum[o1], s1);
            atomicAdd(&d_sumsq[o1], q1);
            atomicAdd(&d_sum[o2], s2);
            atomicAdd(&d_sumsq[o2], q2);
        }
    }
}

// ---------------------------------------------------------------------------
// K5: finalize BN statistics.
// ---------------------------------------------------------------------------
__global__ void k_stats(const float* __restrict__ gamma, const float* __restrict__ beta)
{
    int o = threadIdx.x;
    if (o < CC) {
        float mean = d_sum[o]   * (1.0f / BNT);
        float var  = d_sumsq[o] * (1.0f / BNT) - mean * mean;
        float sc   = gamma[o] * rsqrtf(var + 1e-5f);
        d_scale[o] = sc;
        d_shift[o] = beta[o] - mean * sc;
    }
}

// ---------------------------------------------------------------------------
// K6: out = scale[o]*wy + shift[o] + x
// ---------------------------------------------------------------------------
__global__ __launch_bounds__(256) void k_out(const float* __restrict__ x,
                                             float* __restrict__ out)
{
    size_t i4 = (size_t)blockIdx.x * 256 + threadIdx.x;
    int o = (int)((i4 >> 11) & 255);
    float sc = d_scale[o], sh = d_shift[o];
    float4 w  = *((const float4*)d_wy + i4);
    float4 xv = *((const float4*)x + i4);
    float4 r;
    r.x = fmaf(sc, w.x, sh) + xv.x;
    r.y = fmaf(sc, w.y, sh) + xv.y;
    r.z = fmaf(sc, w.z, sh) + xv.z;
    r.w = fmaf(sc, w.w, sh) + xv.w;
    ((float4*)out)[i4] = r;
}

// ---------------------------------------------------------------------------
extern "C" void kernel_launch(void* const* d_in, const int* in_sizes, int n_in,
                              void* d_out, int out_size)
{
    const float* x     = (const float*)d_in[0];
    const float* tw    = (const float*)d_in[1];
    const float* tb    = (const float*)d_in[2];
    const float* pw    = (const float*)d_in[3];
    const float* pb    = (const float*)d_in[4];
    const float* gw    = (const float*)d_in[5];
    const float* gb    = (const float*)d_in[6];
    const float* ww    = (const float*)d_in[7];
    const float* wb    = (const float*)d_in[8];
    const float* gamma = (const float*)d_in[9];
    const float* beta  = (const float*)d_in[10];
    float* out = (float*)d_out;

    static int smem_set = 0;
    if (!smem_set) {
        cudaFuncSetAttribute(k_conv_hmma, cudaFuncAttributeMaxDynamicSharedMemorySize, SMEM_HMMA);
        cudaFuncSetAttribute(k_wy_hmma,   cudaFuncAttributeMaxDynamicSharedMemorySize, SMEM_HMMA);
        smem_set = 1;
    }

    k_init<<<256, 256>>>();
    k_conv_hmma<<<dim3(TT / 128, 3, BB), 256, SMEM_HMMA>>>(x, tw, tb, pw, pb, gw, gb);
    k_S<<<dim3(32, BB), 256>>>();
    k_M2<<<128, 256>>>(ww);
    k_wy_hmma<<<dim3(TT / 128, 2, BB), 256, SMEM_HMMA>>>(wb);
    k_stats<<<1, 256>>>(gamma, beta);
    k_out<<<8192, 256>>>(x, out);
}

// round 6
// speedup vs baseline: 2.4574x; 1.4176x over previous
#include <cuda_runtime.h>
#include <cstdint>

#define BB 4
#define CC 256
#define CI 128
#define TT 8192
#define NN 4096
#define BNT (BB*TT)

typedef unsigned long long u64;

// Scratch (device globals; no allocation allowed)
__device__ float d_theta[BB*CI*TT];   // 16 MB
__device__ float d_phi[BB*CI*NN];     // 8 MB
__device__ float d_g[BB*CI*NN];       // 8 MB
__device__ float d_S[BB*CI*CI];       // 256 KB
__device__ float d_M[BB*CC*CI];       // 512 KB
__device__ float d_wy[BB*CC*TT];      // 32 MB
__device__ float d_sum[CC];
__device__ float d_sumsq[CC];
__device__ float d_scale[CC];
__device__ float d_shift[CC];

// ---------------- tf32 mma.sync helpers (base PTX, works on sm_103) ---------
__device__ __forceinline__ uint32_t cvt_tf32(float v) {
    uint32_t t; asm("cvt.rn.tf32.f32 %0, %1;" : "=r"(t) : "f"(v)); return t;
}
__device__ __forceinline__ void mma_tf32(float* d, const uint32_t* a, const uint32_t* b) {
    asm("mma.sync.aligned.m16n8k8.row.col.f32.tf32.tf32.f32 "
        "{%0,%1,%2,%3}, {%4,%5,%6,%7}, {%8,%9}, {%0,%1,%2,%3};"
        : "+f"(d[0]), "+f"(d[1]), "+f"(d[2]), "+f"(d[3])
        : "r"(a[0]), "r"(a[1]), "r"(a[2]), "r"(a[3]), "r"(b[0]), "r"(b[1]));
}

// SMEM geometry (dynamic):
//   Af: frag-major A, 64 planes (8 mt x 8 ks) of 132 u32 (pad for conflict-free
//       staging; mainloop reads LDS.128 at plane + lane*4)
//   Bs (conv/wy): [64 k][128 t + pad8 -> 136]  (row stride 136 % 32 == 8:
//       frag-load bank = 8*lq + lr, all 32 distinct -> conflict-free)
//   Bs2 (k_S): [128 ci][64 k + pad4 -> 68]  (frag-load bank = 4*lr + lq)
#define AFPLANE 132
#define AF_U32  (64*AFPLANE)       // 8448
#define PADB    136
#define SMEM_HMMA ((AF_U32 + 64*PADB) * 4)   // (8448 + 8704)*4 = 68608 B

// Stage A chunk (128 rows x 64 k) from row-major W (ld=ldw) into frag-major Af.
// Af[(mt*8+ks)*AFPLANE + lane*4 + j] holds a[j] for that (mt, ks) and lane.
__device__ __forceinline__ void stageA_frag(const float* __restrict__ W, int ldw,
                                            int kc, uint32_t* Af, int tid) {
#pragma unroll
    for (int i = 0; i < 8; i++) {
        int fid = i * 256 + tid;          // 0..2047 float4s
        int o = fid >> 4;                 // 0..127
        int q = fid & 15;                 // k float4 index
        float4 v = *(const float4*)(W + (size_t)o * ldw + kc * 64 + 4 * q);
        int mt = o >> 4, r = o & 15;
        int g = r & 7, hb = r >> 3;       // hb: row-high bit -> j lsb
        int ks = q >> 1, jh = q & 1;      // jh: k-high half -> j msb
        uint32_t* base = Af + (mt * 8 + ks) * AFPLANE + hb + 2 * jh;
        base[(g * 4 + 0) * 4] = cvt_tf32(v.x);
        base[(g * 4 + 1) * 4] = cvt_tf32(v.y);
        base[(g * 4 + 2) * 4] = cvt_tf32(v.z);
        base[(g * 4 + 3) * 4] = cvt_tf32(v.w);
    }
}

// Stage B chunk (64 k x 128 t) from row-major src (ld=lds) into [k][t] padded.
__device__ __forceinline__ void stageB(const float* __restrict__ src, int lds,
                                       int t0, int kc, uint32_t* Bs, int tid) {
#pragma unroll
    for (int i = 0; i < 8; i++) {
        int fid = i * 256 + tid;          // 0..2047
        int k  = fid >> 5;                // 0..63
        int t4 = (fid & 31) << 2;
        float4 v = *(const float4*)(src + (size_t)(kc * 64 + k) * lds + t0 + t4);
        uint32_t* d = Bs + k * PADB + t4;
        *(uint4*)d = make_uint4(cvt_tf32(v.x), cvt_tf32(v.y), cvt_tf32(v.z), cvt_tf32(v.w));
    }
}

// Stage B for k_S: rows are the n-dim (ci), k-dim contiguous in source.
// src[ci][n_off + k], k = 0..63  ->  Bs2[ci*68 + k]
__device__ __forceinline__ void stageBT(const float* __restrict__ src, int lds,
                                        int n_off, uint32_t* Bs2, int tid) {
#pragma unroll
    for (int i = 0; i < 8; i++) {
        int fid = i * 256 + tid;          // 0..2047
        int ci = fid >> 4;                // 0..127
        int q  = fid & 15;
        float4 v = *(const float4*)(src + (size_t)ci * lds + n_off + 4 * q);
        uint32_t* d = Bs2 + ci * 68 + 4 * q;
        *(uint4*)d = make_uint4(cvt_tf32(v.x), cvt_tf32(v.y), cvt_tf32(v.z), cvt_tf32(v.w));
    }
}

// ---------------------------------------------------------------------------
// K0: zero accumulators.
// ---------------------------------------------------------------------------
__global__ void k_init() {
    int i = blockIdx.x * blockDim.x + threadIdx.x;
    if (i < BB*CI*CI) d_S[i] = 0.0f;
    if (i < CC) { d_sum[i] = 0.0f; d_sumsq[i] = 0.0f; }
}

// ---------------------------------------------------------------------------
// K1: fused 1x1 convs via tf32 mma.sync. Block: 128 o x 128 t, K=256.
// 8 warps in 4(o) x 2(t); warp tile 32o x 64t. phi/g maxpooled in epilogue.
// ---------------------------------------------------------------------------
__global__ __launch_bounds__(256) void k_conv_hmma(
    const float* __restrict__ x,
    const float* __restrict__ Wt, const float* __restrict__ bt,
    const float* __restrict__ Wp, const float* __restrict__ bp,
    const float* __restrict__ Wg, const float* __restrict__ bg)
{
    extern __shared__ uint32_t smem[];
    uint32_t* Af = smem;
    uint32_t* Bs = smem + AF_U32;

    const int tid = threadIdx.x;
    const int warp = tid >> 5, lane = tid & 31;
    const int wo = warp >> 1, wt = warp & 1;
    const int b  = blockIdx.z;
    const int w  = blockIdx.y;
    const int t0 = blockIdx.x * 128;

    const float* W    = (w == 0) ? Wt : ((w == 1) ? Wp : Wg);
    const float* bias = (w == 0) ? bt : ((w == 1) ? bp : bg);
    const float* xb   = x + (size_t)b * CC * TT;

    float acc[2][8][4];
#pragma unroll
    for (int mi = 0; mi < 2; mi++)
#pragma unroll
        for (int nt = 0; nt < 8; nt++)
#pragma unroll
            for (int j = 0; j < 4; j++) acc[mi][nt][j] = 0.0f;

    const int lq = lane & 3, lr = lane >> 2;

    for (int kc = 0; kc < 4; kc++) {
        stageA_frag(W, CC, kc, Af, tid);
        stageB(xb, TT, t0, kc, Bs, tid);
        __syncthreads();
#pragma unroll
        for (int ks = 0; ks < 8; ks++) {
            uint32_t a[2][4], bf[8][2];
#pragma unroll
            for (int mi = 0; mi < 2; mi++) {
                int mt = wo * 2 + mi;
                uint4 av = *(const uint4*)(Af + (mt * 8 + ks) * AFPLANE + lane * 4);
                a[mi][0] = av.x; a[mi][1] = av.y; a[mi][2] = av.z; a[mi][3] = av.w;
            }
            int k0 = ks * 8;
            int tb = wt * 64 + lr;
#pragma unroll
            for (int nt = 0; nt < 8; nt++) {
                bf[nt][0] = Bs[(k0 + lq) * PADB + tb + nt * 8];
                bf[nt][1] = Bs[(k0 + 4 + lq) * PADB + tb + nt * 8];
            }
#pragma unroll
            for (int mi = 0; mi < 2; mi++)
#pragma unroll
                for (int nt = 0; nt < 8; nt++)
                    mma_tf32(acc[mi][nt], a[mi], bf[nt]);
        }
        __syncthreads();
    }

    // Epilogue. D frag: d0=D[lr][2lq], d1=D[lr][2lq+1], d2=D[lr+8][2lq], d3=D[lr+8][2lq+1]
    if (w == 0) {
        float* dst = d_theta + (size_t)b * CI * TT;
#pragma unroll
        for (int mi = 0; mi < 2; mi++) {
            int o1 = wo * 32 + mi * 16 + lr;
            int o2 = o1 + 8;
            float bz1 = bias[o1], bz2 = bias[o2];
#pragma unroll
            for (int nt = 0; nt < 8; nt++) {
                int t = t0 + wt * 64 + nt * 8 + 2 * lq;
                *(float2*)(dst + (size_t)o1 * TT + t) =
                    make_float2(acc[mi][nt][0] + bz1, acc[mi][nt][1] + bz1);
                *(float2*)(dst + (size_t)o2 * TT + t) =
                    make_float2(acc[mi][nt][2] + bz2, acc[mi][nt][3] + bz2);
            }
        }
    } else {
        float* dst = ((w == 1) ? d_phi : d_g) + (size_t)b * CI * NN;
#pragma unroll
        for (int mi = 0; mi < 2; mi++) {
            int o1 = wo * 32 + mi * 16 + lr;
            int o2 = o1 + 8;
            float bz1 = bias[o1], bz2 = bias[o2];
#pragma unroll
            for (int nt = 0; nt < 8; nt++) {
                int n = (t0 >> 1) + wt * 32 + nt * 4 + lq;
                dst[(size_t)o1 * NN + n] = fmaxf(acc[mi][nt][0], acc[mi][nt][1]) + bz1;
                dst[(size_t)o2 * NN + n] = fmaxf(acc[mi][nt][2], acc[mi][nt][3]) + bz2;
            }
        }
    }
}

// ---------------------------------------------------------------------------
// K2: S[b,a,ci] = sum_n phi[b,a,n]*g[b,ci,n], via tf32 mma.sync.
// Split-K: 16 slabs of 256 n. Block: 128 a x 128 ci, atomic reduce into d_S.
// ---------------------------------------------------------------------------
__global__ __launch_bounds__(256) void k_S_hmma()
{
    extern __shared__ uint32_t smem[];
    uint32_t* Af  = smem;
    uint32_t* Bs2 = smem + AF_U32;   // 128*68 = 8704 u32

    const int tid = threadIdx.x;
    const int warp = tid >> 5, lane = tid & 31;
    const int wo = warp >> 1, wt = warp & 1;
    const int b    = blockIdx.y;
    const int n0   = blockIdx.x * 256;

    const float* P = d_phi + (size_t)b * CI * NN;
    const float* G = d_g   + (size_t)b * CI * NN;

    float acc[2][8][4];
#pragma unroll
    for (int mi = 0; mi < 2; mi++)
#pragma unroll
        for (int nt = 0; nt < 8; nt++)
#pragma unroll
            for (int j = 0; j < 4; j++) acc[mi][nt][j] = 0.0f;

    const int lq = lane & 3, lr = lane >> 2;

    for (int kc = 0; kc < 4; kc++) {
        stageA_frag(P + n0, NN, kc, Af, tid);
        stageBT(G, NN, n0 + kc * 64, Bs2, tid);
        __syncthreads();
#pragma unroll
        for (int ks = 0; ks < 8; ks++) {
            uint32_t a[2][4], bf[8][2];
#pragma unroll
            for (int mi = 0; mi < 2; mi++) {
                int mt = wo * 2 + mi;
                uint4 av = *(const uint4*)(Af + (mt * 8 + ks) * AFPLANE + lane * 4);
                a[mi][0] = av.x; a[mi][1] = av.y; a[mi][2] = av.z; a[mi][3] = av.w;
            }
            int k0 = ks * 8;
#pragma unroll
            for (int nt = 0; nt < 8; nt++) {
                int n = wt * 64 + nt * 8 + lr;      // ci column
                bf[nt][0] = Bs2[n * 68 + k0 + lq];
                bf[nt][1] = Bs2[n * 68 + k0 + 4 + lq];
            }
#pragma unroll
            for (int mi = 0; mi < 2; mi++)
#pragma unroll
                for (int nt = 0; nt < 8; nt++)
                    mma_tf32(acc[mi][nt], a[mi], bf[nt]);
        }
        __syncthreads();
    }

    float* Sp = d_S + (size_t)b * CI * CI;
#pragma unroll
    for (int mi = 0; mi < 2; mi++) {
        int a1 = wo * 32 + mi * 16 + lr;
        int a2 = a1 + 8;
#pragma unroll
        for (int nt = 0; nt < 8; nt++) {
            int ci = wt * 64 + nt * 8 + 2 * lq;
            atomicAdd(&Sp[(size_t)a1 * CI + ci],     acc[mi][nt][0]);
            atomicAdd(&Sp[(size_t)a1 * CI + ci + 1], acc[mi][nt][1]);
            atomicAdd(&Sp[(size_t)a2 * CI + ci],     acc[mi][nt][2]);
            atomicAdd(&Sp[(size_t)a2 * CI + ci + 1], acc[mi][nt][3]);
        }
    }
}

// ---------------------------------------------------------------------------
// K3: M[b,o,a] = (1/N) * sum_k w_w[o,k] * S[b,a,k]. SMEM-staged small GEMM.
// ---------------------------------------------------------------------------
__global__ __launch_bounds__(256) void k_M2(const float* __restrict__ ww)
{
    __shared__ float ws[32][129];
    __shared__ float ss[32][129];

    const int tid = threadIdx.x;
    const int b  = blockIdx.x >> 5;
    const int ob = (blockIdx.x >> 2) & 7;
    const int ab = blockIdx.x & 3;

#pragma unroll
    for (int i = 0; i < 4; i++) {
        int fid = i * 256 + tid;
        int r = fid >> 5, c4 = fid & 31;
        float4 v = *(const float4*)(ww + (size_t)(ob * 32 + r) * CI + 4 * c4);
        ws[r][4*c4+0] = v.x; ws[r][4*c4+1] = v.y; ws[r][4*c4+2] = v.z; ws[r][4*c4+3] = v.w;
        float4 u = *(const float4*)(d_S + (size_t)b * CI * CI + (size_t)(ab * 32 + r) * CI + 4 * c4);
        ss[r][4*c4+0] = u.x; ss[r][4*c4+1] = u.y; ss[r][4*c4+2] = u.z; ss[r][4*c4+3] = u.w;
    }
    __syncthreads();

    const int ty = tid >> 3;
    const int tx = tid & 7;
    float acc[4] = {0.f, 0.f, 0.f, 0.f};
#pragma unroll
    for (int k = 0; k < CI; k++) {
        float wv = ws[ty][k];
#pragma unroll
        for (int j = 0; j < 4; j++) acc[j] = fmaf(wv, ss[4*tx+j][k], acc[j]);
    }
    const float invN = 1.0f / NN;
    float* Mp = d_M + (size_t)b * CC * CI + (size_t)(ob * 32 + ty) * CI + ab * 32 + 4 * tx;
#pragma unroll
    for (int j = 0; j < 4; j++) Mp[j] = acc[j] * invN;
}

// ---------------------------------------------------------------------------
// K4: wy = M @ theta + w_b via tf32 mma.sync; fused BN partial sums.
// ---------------------------------------------------------------------------
__global__ __launch_bounds__(256) void k_wy_hmma(const float* __restrict__ wb)
{
    extern __shared__ uint32_t smem[];
    uint32_t* Af = smem;
    uint32_t* Bs = smem + AF_U32;

    const int tid = threadIdx.x;
    const int warp = tid >> 5, lane = tid & 31;
    const int wo = warp >> 1, wt = warp & 1;
    const int b  = blockIdx.z;
    const int o0 = blockIdx.y * 128;
    const int t0 = blockIdx.x * 128;

    const float* Mp = d_M + (size_t)b * CC * CI + (size_t)o0 * CI;
    const float* Th = d_theta + (size_t)b * CI * TT;

    float acc[2][8][4];
#pragma unroll
    for (int mi = 0; mi < 2; mi++)
#pragma unroll
        for (int nt = 0; nt < 8; nt++)
#pragma unroll
            for (int j = 0; j < 4; j++) acc[mi][nt][j] = 0.0f;

    const int lq = lane & 3, lr = lane >> 2;

    for (int kc = 0; kc < 2; kc++) {
        stageA_frag(Mp, CI, kc, Af, tid);
        stageB(Th, TT, t0, kc, Bs, tid);
        __syncthreads();
#pragma unroll
        for (int ks = 0; ks < 8; ks++) {
            uint32_t a[2][4], bf[8][2];
#pragma unroll
            for (int mi = 0; mi < 2; mi++) {
                int mt = wo * 2 + mi;
                uint4 av = *(const uint4*)(Af + (mt * 8 + ks) * AFPLANE + lane * 4);
                a[mi][0] = av.x; a[mi][1] = av.y; a[mi][2] = av.z; a[mi][3] = av.w;
            }
            int k0 = ks * 8;
            int tb = wt * 64 + lr;
#pragma unroll
            for (int nt = 0; nt < 8; nt++) {
                bf[nt][0] = Bs[(k0 + lq) * PADB + tb + nt * 8];
                bf[nt][1] = Bs[(k0 + 4 + lq) * PADB + tb + nt * 8];
            }
#pragma unroll
            for (int mi = 0; mi < 2; mi++)
#pragma unroll
                for (int nt = 0; nt < 8; nt++)
                    mma_tf32(acc[mi][nt], a[mi], bf[nt]);
        }
        __syncthreads();
    }

    float* wyp = d_wy + (size_t)b * CC * TT;
#pragma unroll
    for (int mi = 0; mi < 2; mi++) {
        int o1 = o0 + wo * 32 + mi * 16 + lr;
        int o2 = o1 + 8;
        float bz1 = wb[o1], bz2 = wb[o2];
        float s1 = 0.f, q1 = 0.f, s2 = 0.f, q2 = 0.f;
#pragma unroll
        for (int nt = 0; nt < 8; nt++) {
            int t = t0 + wt * 64 + nt * 8 + 2 * lq;
            float v0 = acc[mi][nt][0] + bz1, v1 = acc[mi][nt][1] + bz1;
            float v2 = acc[mi][nt][2] + bz2, v3 = acc[mi][nt][3] + bz2;
            s1 += v0 + v1; q1 = fmaf(v0, v0, q1); q1 = fmaf(v1, v1, q1);
            s2 += v2 + v3; q2 = fmaf(v2, v2, q2); q2 = fmaf(v3, v3, q2);
            *(float2*)(wyp + (size_t)o1 * TT + t) = make_float2(v0, v1);
            *(float2*)(wyp + (size_t)o2 * TT + t) = make_float2(v2, v3);
        }
#pragma unroll
        for (int off = 1; off < 4; off <<= 1) {
            s1 += __shfl_xor_sync(0xffffffffu, s1, off);
            q1 += __shfl_xor_sync(0xffffffffu, q1, off);
            s2 += __shfl_xor_sync(0xffffffffu, s2, off);
            q2 += __shfl_xor_sync(0xffffffffu, q2, off);
        }
        if (lq == 0) {
            atomicAdd(&d_sum[o1], s1);
            atomicAdd(&d_sumsq[o1], q1);
            atomicAdd(&d_sum[o2], s2);
            atomicAdd(&d_sumsq[o2], q2);
        }
    }
}

// ---------------------------------------------------------------------------
// K5: finalize BN statistics.
// ---------------------------------------------------------------------------
__global__ void k_stats(const float* __restrict__ gamma, const float* __restrict__ beta)
{
    int o = threadIdx.x;
    if (o < CC) {
        float mean = d_sum[o]   * (1.0f / BNT);
        float var  = d_sumsq[o] * (1.0f / BNT) - mean * mean;
        float sc   = gamma[o] * rsqrtf(var + 1e-5f);
        d_scale[o] = sc;
        d_shift[o] = beta[o] - mean * sc;
    }
}

// ---------------------------------------------------------------------------
// K6: out = scale[o]*wy + shift[o] + x
// ---------------------------------------------------------------------------
__global__ __launch_bounds__(256) void k_out(const float* __restrict__ x,
                                             float* __restrict__ out)
{
    size_t i4 = (size_t)blockIdx.x * 256 + threadIdx.x;
    int o = (int)((i4 >> 11) & 255);
    float sc = d_scale[o], sh = d_shift[o];
    float4 w  = *((const float4*)d_wy + i4);
    float4 xv = *((const float4*)x + i4);
    float4 r;
    r.x = fmaf(sc, w.x, sh) + xv.x;
    r.y = fmaf(sc, w.y, sh) + xv.y;
    r.z = fmaf(sc, w.z, sh) + xv.z;
    r.w = fmaf(sc, w.w, sh) + xv.w;
    ((float4*)out)[i4] = r;
}

// ---------------------------------------------------------------------------
extern "C" void kernel_launch(void* const* d_in, const int* in_sizes, int n_in,
                              void* d_out, int out_size)
{
    const float* x     = (const float*)d_in[0];
    const float* tw    = (const float*)d_in[1];
    const float* tb    = (const float*)d_in[2];
    const float* pw    = (const float*)d_in[3];
    const float* pb    = (const float*)d_in[4];
    const float* gw    = (const float*)d_in[5];
    const float* gb    = (const float*)d_in[6];
    const float* ww    = (const float*)d_in[7];
    const float* wb    = (const float*)d_in[8];
    const float* gamma = (const float*)d_in[9];
    const float* beta  = (const float*)d_in[10];
    float* out = (float*)d_out;

    static int smem_set = 0;
    if (!smem_set) {
        cudaFuncSetAttribute(k_conv_hmma, cudaFuncAttributeMaxDynamicSharedMemorySize, SMEM_HMMA);
        cudaFuncSetAttribute(k_S_hmma,    cudaFuncAttributeMaxDynamicSharedMemorySize, SMEM_HMMA);
        cudaFuncSetAttribute(k_wy_hmma,   cudaFuncAttributeMaxDynamicSharedMemorySize, SMEM_HMMA);
        smem_set = 1;
    }

    k_init<<<256, 256>>>();
    k_conv_hmma<<<dim3(TT / 128, 3, BB), 256, SMEM_HMMA>>>(x, tw, tb, pw, pb, gw, gb);
    k_S_hmma<<<dim3(16, BB), 256, SMEM_HMMA>>>();
    k_M2<<<128, 256>>>(ww);
    k_wy_hmma<<<dim3(TT / 128, 2, BB), 256, SMEM_HMMA>>>(wb);
    k_stats<<<1, 256>>>(gamma, beta);
    k_out<<<8192, 256>>>(x, out);
}

// round 7
// speedup vs baseline: 2.4594x; 1.0008x over previous
#include <cuda_runtime.h>
#include <cstdint>

#define BB 4
#define CC 256
#define CI 128
#define TT 8192
#define NN 4096
#define BNT (BB*TT)

typedef unsigned long long u64;

// Scratch (device globals; no allocation allowed)
__device__ float d_theta[BB*CI*TT];   // 16 MB
__device__ float d_phi[BB*CI*NN];     // 8 MB
__device__ float d_g[BB*CI*NN];       // 8 MB
__device__ float d_S[BB*CI*CI];       // 256 KB
__device__ float d_M[BB*CC*CI];       // 512 KB
__device__ float d_wy[BB*CC*TT];      // 32 MB
__device__ float d_sum[CC];
__device__ float d_sumsq[CC];
__device__ float d_scale[CC];
__device__ float d_shift[CC];

// ---------------- tf32 mma.sync helper (base PTX, works on sm_103) ----------
// Inputs are RAW fp32 bits (HW truncates to tf32). The systematic truncation
// bias is a per-channel affine distortion of wy, which BatchNorm cancels
// exactly; only rounding-noise-level error survives.
__device__ __forceinline__ void mma_tf32(float* d, const uint32_t* a, const uint32_t* b) {
    asm("mma.sync.aligned.m16n8k8.row.col.f32.tf32.tf32.f32 "
        "{%0,%1,%2,%3}, {%4,%5,%6,%7}, {%8,%9}, {%0,%1,%2,%3};"
        : "+f"(d[0]), "+f"(d[1]), "+f"(d[2]), "+f"(d[3])
        : "r"(a[0]), "r"(a[1]), "r"(a[2]), "r"(a[3]), "r"(b[0]), "r"(b[1]));
}

// SMEM geometry (dynamic):
//   Af: frag-major A, 64 planes (8 mt x 8 ks) of 132 u32
//   Bs (conv/wy): [64 k][128 t + pad8 -> 136]  (conflict-free frag loads)
//   Bs2 (k_S): [128 ci][64 k + pad4 -> 68]
#define AFPLANE 132
#define AF_U32  (64*AFPLANE)       // 8448
#define PADB    136
#define SMEM_HMMA ((AF_U32 + 64*PADB) * 4)   // 68608 B

// Stage A chunk (128 rows x 64 k) from row-major W (ld=ldw) into frag-major Af.
__device__ __forceinline__ void stageA_frag(const float* __restrict__ W, int ldw,
                                            int kc, uint32_t* Af, int tid) {
#pragma unroll
    for (int i = 0; i < 8; i++) {
        int fid = i * 256 + tid;          // 0..2047 float4s
        int o = fid >> 4;                 // 0..127
        int q = fid & 15;                 // k float4 index
        uint4 v = *(const uint4*)(W + (size_t)o * ldw + kc * 64 + 4 * q);
        int mt = o >> 4, r = o & 15;
        int g = r & 7, hb = r >> 3;
        int ks = q >> 1, jh = q & 1;
        uint32_t* base = Af + (mt * 8 + ks) * AFPLANE + hb + 2 * jh;
        base[(g * 4 + 0) * 4] = v.x;
        base[(g * 4 + 1) * 4] = v.y;
        base[(g * 4 + 2) * 4] = v.z;
        base[(g * 4 + 3) * 4] = v.w;
    }
}

// Stage B chunk (64 k x 128 t) from row-major src (ld=lds) into [k][t] padded.
__device__ __forceinline__ void stageB(const float* __restrict__ src, int lds,
                                       int t0, int kc, uint32_t* Bs, int tid) {
#pragma unroll
    for (int i = 0; i < 8; i++) {
        int fid = i * 256 + tid;          // 0..2047
        int k  = fid >> 5;                // 0..63
        int t4 = (fid & 31) << 2;
        uint4 v = *(const uint4*)(src + (size_t)(kc * 64 + k) * lds + t0 + t4);
        *(uint4*)(Bs + k * PADB + t4) = v;
    }
}

// Stage B for k_S: rows are ci, k contiguous in source.
__device__ __forceinline__ void stageBT(const float* __restrict__ src, int lds,
                                        int n_off, uint32_t* Bs2, int tid) {
#pragma unroll
    for (int i = 0; i < 8; i++) {
        int fid = i * 256 + tid;          // 0..2047
        int ci = fid >> 4;                // 0..127
        int q  = fid & 15;
        uint4 v = *(const uint4*)(src + (size_t)ci * lds + n_off + 4 * q);
        *(uint4*)(Bs2 + ci * 68 + 4 * q) = v;
    }
}

// ---------------------------------------------------------------------------
// K0: zero accumulators (S, M, sum, sumsq).
// ---------------------------------------------------------------------------
__global__ void k_init() {
    int i = blockIdx.x * blockDim.x + threadIdx.x;   // 0..65535
    if (i < BB*CI*CI) d_S[i] = 0.0f;
    d_M[2*i]   = 0.0f;
    d_M[2*i+1] = 0.0f;
    if (i < CC) { d_sum[i] = 0.0f; d_sumsq[i] = 0.0f; }
}

// ---------------------------------------------------------------------------
// K1: fused 1x1 convs via tf32 mma.sync. Block: 128 o x 128 t, K=256.
// ---------------------------------------------------------------------------
__global__ __launch_bounds__(256) void k_conv_hmma(
    const float* __restrict__ x,
    const float* __restrict__ Wt, const float* __restrict__ bt,
    const float* __restrict__ Wp, const float* __restrict__ bp,
    const float* __restrict__ Wg, const float* __restrict__ bg)
{
    extern __shared__ uint32_t smem[];
    uint32_t* Af = smem;
    uint32_t* Bs = smem + AF_U32;

    const int tid = threadIdx.x;
    const int warp = tid >> 5, lane = tid & 31;
    const int wo = warp >> 1, wt = warp & 1;
    const int b  = blockIdx.z;
    const int w  = blockIdx.y;
    const int t0 = blockIdx.x * 128;

    const float* W    = (w == 0) ? Wt : ((w == 1) ? Wp : Wg);
    const float* bias = (w == 0) ? bt : ((w == 1) ? bp : bg);
    const float* xb   = x + (size_t)b * CC * TT;

    float acc[2][8][4];
#pragma unroll
    for (int mi = 0; mi < 2; mi++)
#pragma unroll
        for (int nt = 0; nt < 8; nt++)
#pragma unroll
            for (int j = 0; j < 4; j++) acc[mi][nt][j] = 0.0f;

    const int lq = lane & 3, lr = lane >> 2;

    for (int kc = 0; kc < 4; kc++) {
        stageA_frag(W, CC, kc, Af, tid);
        stageB(xb, TT, t0, kc, Bs, tid);
        __syncthreads();
#pragma unroll
        for (int ks = 0; ks < 8; ks++) {
            uint32_t a[2][4], bf[8][2];
#pragma unroll
            for (int mi = 0; mi < 2; mi++) {
                int mt = wo * 2 + mi;
                uint4 av = *(const uint4*)(Af + (mt * 8 + ks) * AFPLANE + lane * 4);
                a[mi][0] = av.x; a[mi][1] = av.y; a[mi][2] = av.z; a[mi][3] = av.w;
            }
            int k0 = ks * 8;
            int tb = wt * 64 + lr;
#pragma unroll
            for (int nt = 0; nt < 8; nt++) {
                bf[nt][0] = Bs[(k0 + lq) * PADB + tb + nt * 8];
                bf[nt][1] = Bs[(k0 + 4 + lq) * PADB + tb + nt * 8];
            }
#pragma unroll
            for (int mi = 0; mi < 2; mi++)
#pragma unroll
                for (int nt = 0; nt < 8; nt++)
                    mma_tf32(acc[mi][nt], a[mi], bf[nt]);
        }
        __syncthreads();
    }

    if (w == 0) {
        float* dst = d_theta + (size_t)b * CI * TT;
#pragma unroll
        for (int mi = 0; mi < 2; mi++) {
            int o1 = wo * 32 + mi * 16 + lr;
            int o2 = o1 + 8;
            float bz1 = bias[o1], bz2 = bias[o2];
#pragma unroll
            for (int nt = 0; nt < 8; nt++) {
                int t = t0 + wt * 64 + nt * 8 + 2 * lq;
                *(float2*)(dst + (size_t)o1 * TT + t) =
                    make_float2(acc[mi][nt][0] + bz1, acc[mi][nt][1] + bz1);
                *(float2*)(dst + (size_t)o2 * TT + t) =
                    make_float2(acc[mi][nt][2] + bz2, acc[mi][nt][3] + bz2);
            }
        }
    } else {
        float* dst = ((w == 1) ? d_phi : d_g) + (size_t)b * CI * NN;
#pragma unroll
        for (int mi = 0; mi < 2; mi++) {
            int o1 = wo * 32 + mi * 16 + lr;
            int o2 = o1 + 8;
            float bz1 = bias[o1], bz2 = bias[o2];
#pragma unroll
            for (int nt = 0; nt < 8; nt++) {
                int n = (t0 >> 1) + wt * 32 + nt * 4 + lq;
                dst[(size_t)o1 * NN + n] = fmaxf(acc[mi][nt][0], acc[mi][nt][1]) + bz1;
                dst[(size_t)o2 * NN + n] = fmaxf(acc[mi][nt][2], acc[mi][nt][3]) + bz2;
            }
        }
    }
}

// ---------------------------------------------------------------------------
// K2: S[b,a,ci] = sum_n phi[b,a,n]*g[b,ci,n], tf32 mma.sync, split-K + atomics.
// ---------------------------------------------------------------------------
__global__ __launch_bounds__(256) void k_S_hmma()
{
    extern __shared__ uint32_t smem[];
    uint32_t* Af  = smem;
    uint32_t* Bs2 = smem + AF_U32;

    const int tid = threadIdx.x;
    const int warp = tid >> 5, lane = tid & 31;
    const int wo = warp >> 1, wt = warp & 1;
    const int b    = blockIdx.y;
    const int n0   = blockIdx.x * 256;

    const float* P = d_phi + (size_t)b * CI * NN;
    const float* G = d_g   + (size_t)b * CI * NN;

    float acc[2][8][4];
#pragma unroll
    for (int mi = 0; mi < 2; mi++)
#pragma unroll
        for (int nt = 0; nt < 8; nt++)
#pragma unroll
            for (int j = 0; j < 4; j++) acc[mi][nt][j] = 0.0f;

    const int lq = lane & 3, lr = lane >> 2;

    for (int kc = 0; kc < 4; kc++) {
        stageA_frag(P + n0, NN, kc, Af, tid);
        stageBT(G, NN, n0 + kc * 64, Bs2, tid);
        __syncthreads();
#pragma unroll
        for (int ks = 0; ks < 8; ks++) {
            uint32_t a[2][4], bf[8][2];
#pragma unroll
            for (int mi = 0; mi < 2; mi++) {
                int mt = wo * 2 + mi;
                uint4 av = *(const uint4*)(Af + (mt * 8 + ks) * AFPLANE + lane * 4);
                a[mi][0] = av.x; a[mi][1] = av.y; a[mi][2] = av.z; a[mi][3] = av.w;
            }
            int k0 = ks * 8;
#pragma unroll
            for (int nt = 0; nt < 8; nt++) {
                int n = wt * 64 + nt * 8 + lr;
                bf[nt][0] = Bs2[n * 68 + k0 + lq];
                bf[nt][1] = Bs2[n * 68 + k0 + 4 + lq];
            }
#pragma unroll
            for (int mi = 0; mi < 2; mi++)
#pragma unroll
                for (int nt = 0; nt < 8; nt++)
                    mma_tf32(acc[mi][nt], a[mi], bf[nt]);
        }
        __syncthreads();
    }

    float* Sp = d_S + (size_t)b * CI * CI;
#pragma unroll
    for (int mi = 0; mi < 2; mi++) {
        int a1 = wo * 32 + mi * 16 + lr;
        int a2 = a1 + 8;
#pragma unroll
        for (int nt = 0; nt < 8; nt++) {
            int ci = wt * 64 + nt * 8 + 2 * lq;
            atomicAdd(&Sp[(size_t)a1 * CI + ci],     acc[mi][nt][0]);
            atomicAdd(&Sp[(size_t)a1 * CI + ci + 1], acc[mi][nt][1]);
            atomicAdd(&Sp[(size_t)a2 * CI + ci],     acc[mi][nt][2]);
            atomicAdd(&Sp[(size_t)a2 * CI + ci + 1], acc[mi][nt][3]);
        }
    }
}

// ---------------------------------------------------------------------------
// K3: M[b,o,a] = (1/N) * sum_k w_w[o,k] * S[b,a,k]. Split-k SMEM GEMM.
// Grid: 256 = b(4) x o-tile(8) x a-tile(4) x k-half(2). atomicAdd into d_M.
// ---------------------------------------------------------------------------
__global__ __launch_bounds__(256) void k_M2(const float* __restrict__ ww)
{
    __shared__ float ws[32][65];
    __shared__ float ss[32][65];

    const int tid = threadIdx.x;
    const int b  = blockIdx.x >> 6;
    const int ob = (blockIdx.x >> 3) & 7;
    const int ab = (blockIdx.x >> 1) & 3;
    const int kh = (blockIdx.x & 1) * 64;

#pragma unroll
    for (int i = 0; i < 2; i++) {
        int fid = i * 256 + tid;       // 0..511
        int r = fid >> 4, c4 = fid & 15;
        float4 v = *(const float4*)(ww + (size_t)(ob * 32 + r) * CI + kh + 4 * c4);
        ws[r][4*c4+0] = v.x; ws[r][4*c4+1] = v.y; ws[r][4*c4+2] = v.z; ws[r][4*c4+3] = v.w;
        float4 u = *(const float4*)(d_S + (size_t)b * CI * CI + (size_t)(ab * 32 + r) * CI + kh + 4 * c4);
        ss[r][4*c4+0] = u.x; ss[r][4*c4+1] = u.y; ss[r][4*c4+2] = u.z; ss[r][4*c4+3] = u.w;
    }
    __syncthreads();

    const int ty = tid >> 3;
    const int tx = tid & 7;
    float acc[4] = {0.f, 0.f, 0.f, 0.f};
#pragma unroll
    for (int k = 0; k < 64; k++) {
        float wv = ws[ty][k];
#pragma unroll
        for (int j = 0; j < 4; j++) acc[j] = fmaf(wv, ss[4*tx+j][k], acc[j]);
    }
    const float invN = 1.0f / NN;
    float* Mp = d_M + (size_t)b * CC * CI + (size_t)(ob * 32 + ty) * CI + ab * 32 + 4 * tx;
#pragma unroll
    for (int j = 0; j < 4; j++) atomicAdd(&Mp[j], acc[j] * invN);
}

// ---------------------------------------------------------------------------
// K4: wy = M @ theta + w_b via tf32 mma.sync; fused BN partial sums.
// ---------------------------------------------------------------------------
__global__ __launch_bounds__(256) void k_wy_hmma(const float* __restrict__ wb)
{
    extern __shared__ uint32_t smem[];
    uint32_t* Af = smem;
    uint32_t* Bs = smem + AF_U32;

    const int tid = threadIdx.x;
    const int warp = tid >> 5, lane = tid & 31;
    const int wo = warp >> 1, wt = warp & 1;
    const int b  = blockIdx.z;
    const int o0 = blockIdx.y * 128;
    const int t0 = blockIdx.x * 128;

    const float* Mp = d_M + (size_t)b * CC * CI + (size_t)o0 * CI;
    const float* Th = d_theta + (size_t)b * CI * TT;

    float acc[2][8][4];
#pragma unroll
    for (int mi = 0; mi < 2; mi++)
#pragma unroll
        for (int nt = 0; nt < 8; nt++)
#pragma unroll
            for (int j = 0; j < 4; j++) acc[mi][nt][j] = 0.0f;

    const int lq = lane & 3, lr = lane >> 2;

    for (int kc = 0; kc < 2; kc++) {
        stageA_frag(Mp, CI, kc, Af, tid);
        stageB(Th, TT, t0, kc, Bs, tid);
        __syncthreads();
#pragma unroll
        for (int ks = 0; ks < 8; ks++) {
            uint32_t a[2][4], bf[8][2];
#pragma unroll
            for (int mi = 0; mi < 2; mi++) {
                int mt = wo * 2 + mi;
                uint4 av = *(const uint4*)(Af + (mt * 8 + ks) * AFPLANE + lane * 4);
                a[mi][0] = av.x; a[mi][1] = av.y; a[mi][2] = av.z; a[mi][3] = av.w;
            }
            int k0 = ks * 8;
            int tb = wt * 64 + lr;
#pragma unroll
            for (int nt = 0; nt < 8; nt++) {
                bf[nt][0] = Bs[(k0 + lq) * PADB + tb + nt * 8];
                bf[nt][1] = Bs[(k0 + 4 + lq) * PADB + tb + nt * 8];
            }
#pragma unroll
            for (int mi = 0; mi < 2; mi++)
#pragma unroll
                for (int nt = 0; nt < 8; nt++)
                    mma_tf32(acc[mi][nt], a[mi], bf[nt]);
        }
        __syncthreads();
    }

    float* wyp = d_wy + (size_t)b * CC * TT;
#pragma unroll
    for (int mi = 0; mi < 2; mi++) {
        int o1 = o0 + wo * 32 + mi * 16 + lr;
        int o2 = o1 + 8;
        float bz1 = wb[o1], bz2 = wb[o2];
        float s1 = 0.f, q1 = 0.f, s2 = 0.f, q2 = 0.f;
#pragma unroll
        for (int nt = 0; nt < 8; nt++) {
            int t = t0 + wt * 64 + nt * 8 + 2 * lq;
            float v0 = acc[mi][nt][0] + bz1, v1 = acc[mi][nt][1] + bz1;
            float v2 = acc[mi][nt][2] + bz2, v3 = acc[mi][nt][3] + bz2;
            s1 += v0 + v1; q1 = fmaf(v0, v0, q1); q1 = fmaf(v1, v1, q1);
            s2 += v2 + v3; q2 = fmaf(v2, v2, q2); q2 = fmaf(v3, v3, q2);
            *(float2*)(wyp + (size_t)o1 * TT + t) = make_float2(v0, v1);
            *(float2*)(wyp + (size_t)o2 * TT + t) = make_float2(v2, v3);
        }
#pragma unroll
        for (int off = 1; off < 4; off <<= 1) {
            s1 += __shfl_xor_sync(0xffffffffu, s1, off);
            q1 += __shfl_xor_sync(0xffffffffu, q1, off);
            s2 += __shfl_xor_sync(0xffffffffu, s2, off);
            q2 += __shfl_xor_sync(0xffffffffu, q2, off);
        }
        if (lq == 0) {
            atomicAdd(&d_sum[o1], s1);
            atomicAdd(&d_sumsq[o1], q1);
            atomicAdd(&d_sum[o2], s2);
            atomicAdd(&d_sumsq[o2], q2);
        }
    }
}

// ---------------------------------------------------------------------------
// K5: finalize BN statistics.
// ---------------------------------------------------------------------------
__global__ void k_stats(const float* __restrict__ gamma, const float* __restrict__ beta)
{
    int o = threadIdx.x;
    if (o < CC) {
        float mean = d_sum[o]   * (1.0f / BNT);
        float var  = d_sumsq[o] * (1.0f / BNT) - mean * mean;
        float sc   = gamma[o] * rsqrtf(var + 1e-5f);
        d_scale[o] = sc;
        d_shift[o] = beta[o] - mean * sc;
    }
}

// ---------------------------------------------------------------------------
// K6: out = scale[o]*wy + shift[o] + x
// ---------------------------------------------------------------------------
__global__ __launch_bounds__(256) void k_out(const float* __restrict__ x,
                                             float* __restrict__ out)
{
    size_t i4 = (size_t)blockIdx.x * 256 + threadIdx.x;
    int o = (int)((i4 >> 11) & 255);
    float sc = d_scale[o], sh = d_shift[o];
    float4 w  = *((const float4*)d_wy + i4);
    float4 xv = *((const float4*)x + i4);
    float4 r;
    r.x = fmaf(sc, w.x, sh) + xv.x;
    r.y = fmaf(sc, w.y, sh) + xv.y;
    r.z = fmaf(sc, w.z, sh) + xv.z;
    r.w = fmaf(sc, w.w, sh) + xv.w;
    ((float4*)out)[i4] = r;
}

// ---------------------------------------------------------------------------
extern "C" void kernel_launch(void* const* d_in, const int* in_sizes, int n_in,
                              void* d_out, int out_size)
{
    const float* x     = (const float*)d_in[0];
    const float* tw    = (const float*)d_in[1];
    const float* tb    = (const float*)d_in[2];
    const float* pw    = (const float*)d_in[3];
    const float* pb    = (const float*)d_in[4];
    const float* gw    = (const float*)d_in[5];
    const float* gb    = (const float*)d_in[6];
    const float* ww    = (const float*)d_in[7];
    const float* wb    = (const float*)d_in[8];
    const float* gamma = (const float*)d_in[9];
    const float* beta  = (const float*)d_in[10];
    float* out = (float*)d_out;

    static int smem_set = 0;
    if (!smem_set) {
        cudaFuncSetAttribute(k_conv_hmma, cudaFuncAttributeMaxDynamicSharedMemorySize, SMEM_HMMA);
        cudaFuncSetAttribute(k_S_hmma,    cudaFuncAttributeMaxDynamicSharedMemorySize, SMEM_HMMA);
        cudaFuncSetAttribute(k_wy_hmma,   cudaFuncAttributeMaxDynamicSharedMemorySize, SMEM_HMMA);
        smem_set = 1;
    }

    k_init<<<256, 256>>>();
    k_conv_hmma<<<dim3(TT / 128, 3, BB), 256, SMEM_HMMA>>>(x, tw, tb, pw, pb, gw, gb);
    k_S_hmma<<<dim3(16, BB), 256, SMEM_HMMA>>>();
    k_M2<<<256, 256>>>(ww);
    k_wy_hmma<<<dim3(TT / 128, 2, BB), 256, SMEM_HMMA>>>(wb);
    k_stats<<<1, 256>>>(gamma, beta);
    k_out<<<8192, 256>>>(x, out);
}

// round 8
// speedup vs baseline: 2.6485x; 1.0769x over previous
#include <cuda_runtime.h>
#include <cstdint>

#define BB 4
#define CC 256
#define CI 128
#define TT 8192
#define NN 4096
#define BNT (BB*TT)

// Scratch (device globals; no allocation allowed)
__device__ float d_theta[BB*CI*TT];   // 16 MB
__device__ float d_phi[BB*CI*NN];     // 8 MB
__device__ float d_g[BB*CI*NN];       // 8 MB
__device__ float d_S[BB*CI*CI];       // 256 KB
__device__ float d_M[BB*CC*CI];       // 512 KB
__device__ float d_wy[BB*CC*TT];      // 32 MB
__device__ float d_sum[CC];
__device__ float d_sumsq[CC];
__device__ float d_scale[CC];
__device__ float d_shift[CC];

// ---------------- tf32 mma.sync helper (raw fp32 bits; BN cancels the
// systematic truncation bias as a per-channel affine distortion) ------------
__device__ __forceinline__ void mma_tf32(float* d, const uint32_t* a, const uint32_t* b) {
    asm("mma.sync.aligned.m16n8k8.row.col.f32.tf32.tf32.f32 "
        "{%0,%1,%2,%3}, {%4,%5,%6,%7}, {%8,%9}, {%0,%1,%2,%3};"
        : "+f"(d[0]), "+f"(d[1]), "+f"(d[2]), "+f"(d[3])
        : "r"(a[0]), "r"(a[1]), "r"(a[2]), "r"(a[3]), "r"(b[0]), "r"(b[1]));
}

// ---------------- cp.async helpers ------------------------------------------
__device__ __forceinline__ uint32_t smem_u32(const void* p) {
    uint32_t a;
    asm("{ .reg .u64 t; cvta.to.shared.u64 t, %1; cvt.u32.u64 %0, t; }" : "=r"(a) : "l"(p));
    return a;
}
__device__ __forceinline__ void cp16(uint32_t dst, const void* src) {
    asm volatile("cp.async.cg.shared.global [%0], [%1], 16;" :: "r"(dst), "l"(src));
}
#define CP_COMMIT() asm volatile("cp.async.commit_group;" ::: "memory")
#define CP_WAIT1()  asm volatile("cp.async.wait_group 1;" ::: "memory")
#define CP_WAIT0()  asm volatile("cp.async.wait_group 0;" ::: "memory")

// SMEM geometry: per stage, A chunk 128 rows x 32 k (row-major, pad 4) and
// B chunk 32 k x 128 cols (pad 8). Two stages (double buffer).
//   A frag loads: bank = (4*lr + lq + 8ks) % 32  -> conflict-free
//   B frag loads: bank = (8*lq + lr) % 32        -> conflict-free
//   S's B (row-major like A): bank = (4*lr + lq) -> conflict-free
#define RPA 36
#define RPB 136
#define ASZ (128*RPA)          // 4608 u32
#define BSZ (32*RPB)           // 4352 u32
#define STG_C (ASZ + BSZ)      // 8960 u32
#define SMEM_CONV (2*STG_C*4)  // 71680 B
#define STG_S (ASZ + ASZ)      // 9216 u32
#define SMEM_S (2*STG_S*4)     // 73728 B

// Stage 128 rows x 32 floats (A-style / S's B-style), cp.async.
__device__ __forceinline__ void stage128x32(uint32_t dstb, const float* __restrict__ src,
                                            int lds, int koff, int tid) {
#pragma unroll
    for (int i = 0; i < 4; i++) {
        int fid = i * 256 + tid;        // 0..1023
        int r = fid >> 3, q = fid & 7;
        cp16(dstb + (uint32_t)(r * RPA + q * 4) * 4,
             src + (size_t)r * lds + koff + q * 4);
    }
}
// Stage 32 k-rows x 128 floats (B-style), cp.async.
__device__ __forceinline__ void stage32x128(uint32_t dstb, const float* __restrict__ src,
                                            int lds, int koff, int t0, int tid) {
#pragma unroll
    for (int i = 0; i < 4; i++) {
        int fid = i * 256 + tid;        // 0..1023
        int k = fid >> 5, t4 = (fid & 31) << 2;
        cp16(dstb + (uint32_t)(k * RPB + t4) * 4,
             src + (size_t)(koff + k) * lds + t0 + t4);
    }
}

// ---------------------------------------------------------------------------
// K0: zero accumulators (S, M, sum, sumsq).
// ---------------------------------------------------------------------------
__global__ void k_init() {
    int i = blockIdx.x * blockDim.x + threadIdx.x;   // 0..65535
    if (i < BB*CI*CI) d_S[i] = 0.0f;
    d_M[2*i]   = 0.0f;
    d_M[2*i+1] = 0.0f;
    if (i < CC) { d_sum[i] = 0.0f; d_sumsq[i] = 0.0f; }
}

// ---------------------------------------------------------------------------
// K1: fused 1x1 convs via tf32 mma.sync + cp.async double buffer.
// Block: 128 o x 128 t, K=256 in 8 chunks of 32.
// ---------------------------------------------------------------------------
__global__ void __launch_bounds__(256, 2) k_conv_hmma(
    const float* __restrict__ x,
    const float* __restrict__ Wt, const float* __restrict__ bt,
    const float* __restrict__ Wp, const float* __restrict__ bp,
    const float* __restrict__ Wg, const float* __restrict__ bg)
{
    extern __shared__ uint32_t smem[];
    const uint32_t smb = smem_u32(smem);

    const int tid = threadIdx.x;
    const int warp = tid >> 5, lane = tid & 31;
    const int wo = warp >> 1, wt = warp & 1;
    const int b  = blockIdx.z;
    const int w  = blockIdx.y;
    const int t0 = blockIdx.x * 128;

    const float* W    = (w == 0) ? Wt : ((w == 1) ? Wp : Wg);
    const float* bias = (w == 0) ? bt : ((w == 1) ? bp : bg);
    const float* xb   = x + (size_t)b * CC * TT;

    float acc[2][8][4];
#pragma unroll
    for (int mi = 0; mi < 2; mi++)
#pragma unroll
        for (int nt = 0; nt < 8; nt++)
#pragma unroll
            for (int j = 0; j < 4; j++) acc[mi][nt][j] = 0.0f;

    const int lq = lane & 3, lr = lane >> 2;
    const int NC = 8;

    // prologue: stage chunk 0
    stage128x32(smb, W, CC, 0, tid);
    stage32x128(smb + ASZ * 4, xb, TT, 0, t0, tid);
    CP_COMMIT();

    for (int kc = 0; kc < NC; kc++) {
        if (kc + 1 < NC) {
            uint32_t ab = smb + (uint32_t)(((kc + 1) & 1) * STG_C) * 4;
            stage128x32(ab, W, CC, (kc + 1) * 32, tid);
            stage32x128(ab + ASZ * 4, xb, TT, (kc + 1) * 32, t0, tid);
            CP_COMMIT();
            CP_WAIT1();
        } else {
            CP_WAIT0();
        }
        __syncthreads();
        const uint32_t* As = smem + (kc & 1) * STG_C;
        const uint32_t* Bs = As + ASZ;
#pragma unroll
        for (int ks = 0; ks < 4; ks++) {
            int k0 = ks * 8;
            uint32_t a[2][4], bf[8][2];
#pragma unroll
            for (int mi = 0; mi < 2; mi++) {
                int ro = (wo * 2 + mi) * 16;
                a[mi][0] = As[(ro + lr) * RPA + k0 + lq];
                a[mi][1] = As[(ro + lr + 8) * RPA + k0 + lq];
                a[mi][2] = As[(ro + lr) * RPA + k0 + 4 + lq];
                a[mi][3] = As[(ro + lr + 8) * RPA + k0 + 4 + lq];
            }
            int tb = wt * 64 + lr;
#pragma unroll
            for (int nt = 0; nt < 8; nt++) {
                bf[nt][0] = Bs[(k0 + lq) * RPB + tb + nt * 8];
                bf[nt][1] = Bs[(k0 + 4 + lq) * RPB + tb + nt * 8];
            }
#pragma unroll
            for (int mi = 0; mi < 2; mi++)
#pragma unroll
                for (int nt = 0; nt < 8; nt++)
                    mma_tf32(acc[mi][nt], a[mi], bf[nt]);
        }
        __syncthreads();
    }

    // Epilogue. D frag: d0=D[lr][2lq], d1=D[lr][2lq+1], d2=D[lr+8][2lq], d3=D[lr+8][2lq+1]
    if (w == 0) {
        float* dst = d_theta + (size_t)b * CI * TT;
#pragma unroll
        for (int mi = 0; mi < 2; mi++) {
            int o1 = wo * 32 + mi * 16 + lr;
            int o2 = o1 + 8;
            float bz1 = bias[o1], bz2 = bias[o2];
#pragma unroll
            for (int nt = 0; nt < 8; nt++) {
                int t = t0 + wt * 64 + nt * 8 + 2 * lq;
                *(float2*)(dst + (size_t)o1 * TT + t) =
                    make_float2(acc[mi][nt][0] + bz1, acc[mi][nt][1] + bz1);
                *(float2*)(dst + (size_t)o2 * TT + t) =
                    make_float2(acc[mi][nt][2] + bz2, acc[mi][nt][3] + bz2);
            }
        }
    } else {
        float* dst = ((w == 1) ? d_phi : d_g) + (size_t)b * CI * NN;
#pragma unroll
        for (int mi = 0; mi < 2; mi++) {
            int o1 = wo * 32 + mi * 16 + lr;
            int o2 = o1 + 8;
            float bz1 = bias[o1], bz2 = bias[o2];
#pragma unroll
            for (int nt = 0; nt < 8; nt++) {
                int n = (t0 >> 1) + wt * 32 + nt * 4 + lq;
                dst[(size_t)o1 * NN + n] = fmaxf(acc[mi][nt][0], acc[mi][nt][1]) + bz1;
                dst[(size_t)o2 * NN + n] = fmaxf(acc[mi][nt][2], acc[mi][nt][3]) + bz2;
            }
        }
    }
}

// ---------------------------------------------------------------------------
// K2: S[b,a,ci] = sum_n phi[b,a,n]*g[b,ci,n], tf32 mma + cp.async pipeline.
// Split-K: 16 slabs of 256 n (8 chunks of 32). Atomic reduce into d_S.
// ---------------------------------------------------------------------------
__global__ void __launch_bounds__(256, 2) k_S_hmma()
{
    extern __shared__ uint32_t smem[];
    const uint32_t smb = smem_u32(smem);

    const int tid = threadIdx.x;
    const int warp = tid >> 5, lane = tid & 31;
    const int wo = warp >> 1, wt = warp & 1;
    const int b  = blockIdx.y;
    const int n0 = blockIdx.x * 256;

    const float* P = d_phi + (size_t)b * CI * NN;
    const float* G = d_g   + (size_t)b * CI * NN;

    float acc[2][8][4];
#pragma unroll
    for (int mi = 0; mi < 2; mi++)
#pragma unroll
        for (int nt = 0; nt < 8; nt++)
#pragma unroll
            for (int j = 0; j < 4; j++) acc[mi][nt][j] = 0.0f;

    const int lq = lane & 3, lr = lane >> 2;
    const int NC = 8;

    stage128x32(smb, P, NN, n0, tid);
    stage128x32(smb + ASZ * 4, G, NN, n0, tid);
    CP_COMMIT();

    for (int kc = 0; kc < NC; kc++) {
        if (kc + 1 < NC) {
            uint32_t ab = smb + (uint32_t)(((kc + 1) & 1) * STG_S) * 4;
            stage128x32(ab, P, NN, n0 + (kc + 1) * 32, tid);
            stage128x32(ab + ASZ * 4, G, NN, n0 + (kc + 1) * 32, tid);
            CP_COMMIT();
            CP_WAIT1();
        } else {
            CP_WAIT0();
        }
        __syncthreads();
        const uint32_t* As  = smem + (kc & 1) * STG_S;
        const uint32_t* Bs2 = As + ASZ;
#pragma unroll
        for (int ks = 0; ks < 4; ks++) {
            int k0 = ks * 8;
            uint32_t a[2][4], bf[8][2];
#pragma unroll
            for (int mi = 0; mi < 2; mi++) {
                int ro = (wo * 2 + mi) * 16;
                a[mi][0] = As[(ro + lr) * RPA + k0 + lq];
                a[mi][1] = As[(ro + lr + 8) * RPA + k0 + lq];
                a[mi][2] = As[(ro + lr) * RPA + k0 + 4 + lq];
                a[mi][3] = As[(ro + lr + 8) * RPA + k0 + 4 + lq];
            }
#pragma unroll
            for (int nt = 0; nt < 8; nt++) {
                int n = wt * 64 + nt * 8 + lr;
                bf[nt][0] = Bs2[n * RPA + k0 + lq];
                bf[nt][1] = Bs2[n * RPA + k0 + 4 + lq];
            }
#pragma unroll
            for (int mi = 0; mi < 2; mi++)
#pragma unroll
                for (int nt = 0; nt < 8; nt++)
                    mma_tf32(acc[mi][nt], a[mi], bf[nt]);
        }
        __syncthreads();
    }

    float* Sp = d_S + (size_t)b * CI * CI;
#pragma unroll
    for (int mi = 0; mi < 2; mi++) {
        int a1 = wo * 32 + mi * 16 + lr;
        int a2 = a1 + 8;
#pragma unroll
        for (int nt = 0; nt < 8; nt++) {
            int ci = wt * 64 + nt * 8 + 2 * lq;
            atomicAdd(&Sp[(size_t)a1 * CI + ci],     acc[mi][nt][0]);
            atomicAdd(&Sp[(size_t)a1 * CI + ci + 1], acc[mi][nt][1]);
            atomicAdd(&Sp[(size_t)a2 * CI + ci],     acc[mi][nt][2]);
            atomicAdd(&Sp[(size_t)a2 * CI + ci + 1], acc[mi][nt][3]);
        }
    }
}

// ---------------------------------------------------------------------------
// K3: M[b,o,a] = (1/N) * sum_k w_w[o,k] * S[b,a,k]. Split-k SMEM GEMM.
// ---------------------------------------------------------------------------
__global__ __launch_bounds__(256) void k_M2(const float* __restrict__ ww)
{
    __shared__ float ws[32][65];
    __shared__ float ss[32][65];

    const int tid = threadIdx.x;
    const int b  = blockIdx.x >> 6;
    const int ob = (blockIdx.x >> 3) & 7;
    const int ab = (blockIdx.x >> 1) & 3;
    const int kh = (blockIdx.x & 1) * 64;

#pragma unroll
    for (int i = 0; i < 2; i++) {
        int fid = i * 256 + tid;
        int r = fid >> 4, c4 = fid & 15;
        float4 v = *(const float4*)(ww + (size_t)(ob * 32 + r) * CI + kh + 4 * c4);
        ws[r][4*c4+0] = v.x; ws[r][4*c4+1] = v.y; ws[r][4*c4+2] = v.z; ws[r][4*c4+3] = v.w;
        float4 u = *(const float4*)(d_S + (size_t)b * CI * CI + (size_t)(ab * 32 + r) * CI + kh + 4 * c4);
        ss[r][4*c4+0] = u.x; ss[r][4*c4+1] = u.y; ss[r][4*c4+2] = u.z; ss[r][4*c4+3] = u.w;
    }
    __syncthreads();

    const int ty = tid >> 3;
    const int tx = tid & 7;
    float acc[4] = {0.f, 0.f, 0.f, 0.f};
#pragma unroll
    for (int k = 0; k < 64; k++) {
        float wv = ws[ty][k];
#pragma unroll
        for (int j = 0; j < 4; j++) acc[j] = fmaf(wv, ss[4*tx+j][k], acc[j]);
    }
    const float invN = 1.0f / NN;
    float* Mp = d_M + (size_t)b * CC * CI + (size_t)(ob * 32 + ty) * CI + ab * 32 + 4 * tx;
#pragma unroll
    for (int j = 0; j < 4; j++) atomicAdd(&Mp[j], acc[j] * invN);
}

// ---------------------------------------------------------------------------
// K4: wy = M @ theta + w_b via tf32 mma + cp.async pipeline; fused BN sums.
// Block: 128 o x 128 t, K=128 in 4 chunks of 32.
// ---------------------------------------------------------------------------
__global__ void __launch_bounds__(256, 2) k_wy_hmma(const float* __restrict__ wb)
{
    extern __shared__ uint32_t smem[];
    const uint32_t smb = smem_u32(smem);

    const int tid = threadIdx.x;
    const int warp = tid >> 5, lane = tid & 31;
    const int wo = warp >> 1, wt = warp & 1;
    const int b  = blockIdx.z;
    const int o0 = blockIdx.y * 128;
    const int t0 = blockIdx.x * 128;

    const float* Mp = d_M + (size_t)b * CC * CI + (size_t)o0 * CI;
    const float* Th = d_theta + (size_t)b * CI * TT;

    float acc[2][8][4];
#pragma unroll
    for (int mi = 0; mi < 2; mi++)
#pragma unroll
        for (int nt = 0; nt < 8; nt++)
#pragma unroll
            for (int j = 0; j < 4; j++) acc[mi][nt][j] = 0.0f;

    const int lq = lane & 3, lr = lane >> 2;
    const int NC = 4;

    stage128x32(smb, Mp, CI, 0, tid);
    stage32x128(smb + ASZ * 4, Th, TT, 0, t0, tid);
    CP_COMMIT();

    for (int kc = 0; kc < NC; kc++) {
        if (kc + 1 < NC) {
            uint32_t ab = smb + (uint32_t)(((kc + 1) & 1) * STG_C) * 4;
            stage128x32(ab, Mp, CI, (kc + 1) * 32, tid);
            stage32x128(ab + ASZ * 4, Th, TT, (kc + 1) * 32, t0, tid);
            CP_COMMIT();
            CP_WAIT1();
        } else {
            CP_WAIT0();
        }
        __syncthreads();
        const uint32_t* As = smem + (kc & 1) * STG_C;
        const uint32_t* Bs = As + ASZ;
#pragma unroll
        for (int ks = 0; ks < 4; ks++) {
            int k0 = ks * 8;
            uint32_t a[2][4], bf[8][2];
#pragma unroll
            for (int mi = 0; mi < 2; mi++) {
                int ro = (wo * 2 + mi) * 16;
                a[mi][0] = As[(ro + lr) * RPA + k0 + lq];
                a[mi][1] = As[(ro + lr + 8) * RPA + k0 + lq];
                a[mi][2] = As[(ro + lr) * RPA + k0 + 4 + lq];
                a[mi][3] = As[(ro + lr + 8) * RPA + k0 + 4 + lq];
            }
            int tb = wt * 64 + lr;
#pragma unroll
            for (int nt = 0; nt < 8; nt++) {
                bf[nt][0] = Bs[(k0 + lq) * RPB + tb + nt * 8];
                bf[nt][1] = Bs[(k0 + 4 + lq) * RPB + tb + nt * 8];
            }
#pragma unroll
            for (int mi = 0; mi < 2; mi++)
#pragma unroll
                for (int nt = 0; nt < 8; nt++)
                    mma_tf32(acc[mi][nt], a[mi], bf[nt]);
        }
        __syncthreads();
    }

    float* wyp = d_wy + (size_t)b * CC * TT;
#pragma unroll
    for (int mi = 0; mi < 2; mi++) {
        int o1 = o0 + wo * 32 + mi * 16 + lr;
        int o2 = o1 + 8;
        float bz1 = wb[o1], bz2 = wb[o2];
        float s1 = 0.f, q1 = 0.f, s2 = 0.f, q2 = 0.f;
#pragma unroll
        for (int nt = 0; nt < 8; nt++) {
            int t = t0 + wt * 64 + nt * 8 + 2 * lq;
            float v0 = acc[mi][nt][0] + bz1, v1 = acc[mi][nt][1] + bz1;
            float v2 = acc[mi][nt][2] + bz2, v3 = acc[mi][nt][3] + bz2;
            s1 += v0 + v1; q1 = fmaf(v0, v0, q1); q1 = fmaf(v1, v1, q1);
            s2 += v2 + v3; q2 = fmaf(v2, v2, q2); q2 = fmaf(v3, v3, q2);
            *(float2*)(wyp + (size_t)o1 * TT + t) = make_float2(v0, v1);
            *(float2*)(wyp + (size_t)o2 * TT + t) = make_float2(v2, v3);
        }
#pragma unroll
        for (int off = 1; off < 4; off <<= 1) {
            s1 += __shfl_xor_sync(0xffffffffu, s1, off);
            q1 += __shfl_xor_sync(0xffffffffu, q1, off);
            s2 += __shfl_xor_sync(0xffffffffu, s2, off);
            q2 += __shfl_xor_sync(0xffffffffu, q2, off);
        }
        if (lq == 0) {
            atomicAdd(&d_sum[o1], s1);
            atomicAdd(&d_sumsq[o1], q1);
            atomicAdd(&d_sum[o2], s2);
            atomicAdd(&d_sumsq[o2], q2);
        }
    }
}

// ---------------------------------------------------------------------------
// K5: finalize BN statistics.
// ---------------------------------------------------------------------------
__global__ void k_stats(const float* __restrict__ gamma, const float* __restrict__ beta)
{
    int o = threadIdx.x;
    if (o < CC) {
        float mean = d_sum[o]   * (1.0f / BNT);
        float var  = d_sumsq[o] * (1.0f / BNT) - mean * mean;
        float sc   = gamma[o] * rsqrtf(var + 1e-5f);
        d_scale[o] = sc;
        d_shift[o] = beta[o] - mean * sc;
    }
}

// ---------------------------------------------------------------------------
// K6: out = scale[o]*wy + shift[o] + x
// ---------------------------------------------------------------------------
__global__ __launch_bounds__(256) void k_out(const float* __restrict__ x,
                                             float* __restrict__ out)
{
    size_t i4 = (size_t)blockIdx.x * 256 + threadIdx.x;
    int o = (int)((i4 >> 11) & 255);
    float sc = d_scale[o], sh = d_shift[o];
    float4 w  = *((const float4*)d_wy + i4);
    float4 xv = *((const float4*)x + i4);
    float4 r;
    r.x = fmaf(sc, w.x, sh) + xv.x;
    r.y = fmaf(sc, w.y, sh) + xv.y;
    r.z = fmaf(sc, w.z, sh) + xv.z;
    r.w = fmaf(sc, w.w, sh) + xv.w;
    ((float4*)out)[i4] = r;
}

// ---------------------------------------------------------------------------
extern "C" void kernel_launch(void* const* d_in, const int* in_sizes, int n_in,
                              void* d_out, int out_size)
{
    const float* x     = (const float*)d_in[0];
    const float* tw    = (const float*)d_in[1];
    const float* tb    = (const float*)d_in[2];
    const float* pw    = (const float*)d_in[3];
    const float* pb    = (const float*)d_in[4];
    const float* gw    = (const float*)d_in[5];
    const float* gb    = (const float*)d_in[6];
    const float* ww    = (const float*)d_in[7];
    const float* wb    = (const float*)d_in[8];
    const float* gamma = (const float*)d_in[9];
    const float* beta  = (const float*)d_in[10];
    float* out = (float*)d_out;

    static int smem_set = 0;
    if (!smem_set) {
        cudaFuncSetAttribute(k_conv_hmma, cudaFuncAttributeMaxDynamicSharedMemorySize, SMEM_CONV);
        cudaFuncSetAttribute(k_S_hmma,    cudaFuncAttributeMaxDynamicSharedMemorySize, SMEM_S);
        cudaFuncSetAttribute(k_wy_hmma,   cudaFuncAttributeMaxDynamicSharedMemorySize, SMEM_CONV);
        smem_set = 1;
    }

    k_init<<<256, 256>>>();
    k_conv_hmma<<<dim3(TT / 128, 3, BB), 256, SMEM_CONV>>>(x, tw, tb, pw, pb, gw, gb);
    k_S_hmma<<<dim3(16, BB), 256, SMEM_S>>>();
    k_M2<<<256, 256>>>(ww);
    k_wy_hmma<<<dim3(TT / 128, 2, BB), 256, SMEM_CONV>>>(wb);
    k_stats<<<1, 256>>>(gamma, beta);
    k_out<<<8192, 256>>>(x, out);
}